// round 11
// baseline (speedup 1.0000x reference)
#include <cuda_runtime.h>
#include <cuda_bf16.h>
#include <math.h>

// ---------------- problem constants ----------------
#define S_LEN   8192
#define L_CHARS 16
#define CHAR_DIM 64
#define WORD_DIM 256
#define CHAR_HID 128
#define WORD_HID 512
#define N_TAG   64
#define CK      192              // CHAR_DIM + CHAR_HID (char gemm K)
#define WK      384              // WORD_DIM + CHAR_HID (word input gemm K)
#define GW2     64               // persistent CTAs for word LSTM
#define TPB2    256              // 8 warps = 8 hidden units per CTA
#define SENT    0x7fbadbadu     // NaN-pattern sentinel (h can never be NaN)
#define HP_STRIDE 2048           // padded h row: 64 chunks x 32 floats (128B lines)

// ---------------- device scratch (no cudaMalloc allowed) ----------------
__device__ __align__(16) float g_A[S_LEN * CK];        // char gemm input [ce_t | h]
__device__ __align__(16) float g_gates[S_LEN * 512];   // char gates
__device__ __align__(16) float g_c[S_LEN * CHAR_HID];  // char cell state
__device__ __align__(16) float g_cf[S_LEN * CHAR_HID]; // char features
__device__ __align__(16) float g_Wc[512 * CK];         // concat [c_Wih | c_Whh]
__device__ __align__(16) float g_bc[512];              // c_bih + c_bhh
__device__ __align__(16) float g_bw[2048];             // w_bih + w_bhh
__device__ __align__(16) float g_F[S_LEN * WK];        // word feats [we | cf]
__device__ __align__(16) float g_wg[S_LEN * 2048];     // word input gates (unit f4)
__device__ __align__(16) float g_hp[(S_LEN + 1) * HP_STRIDE]; // padded h (poll target)
__device__ __align__(16) float g_hd[(S_LEN + 1) * 512];       // dense h (classifier)

__device__ __forceinline__ float sigmoidf_(float x) { return 1.f / (1.f + expf(-x)); }

// Accurate fast activations (2-ulp MUFU exp + fast divide).
// tanh.approx.f32 (5e-4 abs err) amplifies ~600x through the 8192-step
// recurrence -> 0.316 rel_err (R4). These stay at ~1e-7 per step.
__device__ __forceinline__ float sig_acc(float x) {
    x = fminf(fmaxf(x, -30.f), 30.f);
    float e = __expf(-x);
    return __fdividef(1.f, 1.f + e);
}
__device__ __forceinline__ float tanh_acc(float x) {
    x = fminf(fmaxf(x, -15.f), 15.f);
    float e = __expf(2.f * x);
    return __fdividef(e - 1.f, e + 1.f);
}
__device__ __forceinline__ float4 ldcg_f4(const float* p) {
    float4 v;
    asm volatile("ld.global.cg.v4.f32 {%0,%1,%2,%3}, [%4];"
                 : "=f"(v.x), "=f"(v.y), "=f"(v.z), "=f"(v.w) : "l"(p) : "memory");
    return v;
}
// VOLATILE poll load (ptxas may legally hoist weak loads out of spin loops --
// the R6 failure). Integer regs: no float compare on the NaN sentinel.
__device__ __forceinline__ uint4 ldvol_u4(const float* p) {
    uint4 v;
    asm volatile("ld.volatile.global.v4.b32 {%0,%1,%2,%3}, [%4];"
                 : "=r"(v.x), "=r"(v.y), "=r"(v.z), "=r"(v.w) : "l"(p) : "memory");
    return v;
}
__device__ __forceinline__ unsigned any_sent_u(uint4 v) {
    return (unsigned)(v.x == SENT) | (unsigned)(v.y == SENT) |
           (unsigned)(v.z == SENT) | (unsigned)(v.w == SENT);
}
// Packed dual-fp32 FMA (sm_103a FFMA2; only reachable via explicit PTX --
// ptxas never auto-fuses). Numerically exact: two independent fp32 FMAs.
__device__ __forceinline__ float2 fma2_(float2 a, float2 b, float2 c) {
    unsigned long long ra, rb, rc, rd;
    memcpy(&ra, &a, 8); memcpy(&rb, &b, 8); memcpy(&rc, &c, 8);
    asm("fma.rn.f32x2 %0, %1, %2, %3;" : "=l"(rd) : "l"(ra), "l"(rb), "l"(rc));
    float2 d; memcpy(&d, &rd, 8);
    return d;
}

// ---------------- prep: concat weights, biases, init buffers ----------------
__global__ void prep_kernel(const int* __restrict__ chars,
                            const float* __restrict__ char_embed,
                            const float* __restrict__ c_Wih,
                            const float* __restrict__ c_Whh,
                            const float* __restrict__ c_bih,
                            const float* __restrict__ c_bhh,
                            const float* __restrict__ w_bih,
                            const float* __restrict__ w_bhh) {
    int tid = blockIdx.x * blockDim.x + threadIdx.x;
    int stride = gridDim.x * blockDim.x;
    for (int i = tid; i < 512 * CK; i += stride) {
        int j = i / CK, k = i - j * CK;
        g_Wc[i] = (k < CHAR_DIM) ? c_Wih[j * CHAR_DIM + k]
                                 : c_Whh[j * CHAR_HID + (k - CHAR_DIM)];
    }
    for (int i = tid; i < 512; i += stride) g_bc[i] = c_bih[i] + c_bhh[i];
    for (int i = tid; i < 2048; i += stride) g_bw[i] = w_bih[i] + w_bhh[i];
    for (int i = tid; i < S_LEN * CHAR_HID; i += stride) g_c[i] = 0.f;
    // padded h: row 0 = zeros (initial state), rows 1..S = sentinel
    // (re-poisoned on every launch / graph replay)
    for (int i = tid; i < (S_LEN + 1) * HP_STRIDE; i += stride)
        ((unsigned*)g_hp)[i] = (i < HP_STRIDE) ? 0u : SENT;
    for (int i = tid; i < 512; i += stride) g_hd[i] = 0.f;  // dense row 0
    // char gemm input for t=0: ce in cols [0,64), zeros (h0) in [64,192)
    for (int i = tid; i < S_LEN * CK; i += stride) {
        int b = i / CK, k = i - b * CK;
        g_A[i] = (k < CHAR_DIM)
                   ? char_embed[chars[b * L_CHARS + 0] * CHAR_DIM + k]
                   : 0.f;
    }
}

// ---------------- generic fp32 GEMM: C = A(MxK) * B(NxK)^T + bias ----------------
// BM=128 BN=64 BK=16, 256 threads, 8x4 per-thread tile.
// mode 0: C[row*ldc+col] = acc + bias[col]
// mode 1: word-gate unit-blocked store: dst = (col&511)*4 + (col>>9)
__global__ void __launch_bounds__(256) gemm_bias(const float* __restrict__ A,
                                                 const float* __restrict__ B,
                                                 const float* __restrict__ bias,
                                                 float* __restrict__ C,
                                                 int K, int ldc, int mode) {
    __shared__ float sA[2][16][129];
    __shared__ float sB[2][16][65];
    const int bm = blockIdx.x << 7;
    const int bn = blockIdx.y << 6;
    const int tid = threadIdx.x;
    const int tx = tid & 15;
    const int ty = tid >> 4;
    const int lrow = tid >> 2;
    const int kq = (tid & 3) << 2;

    const float* Aptr = A + (size_t)(bm + lrow) * K + kq;
    const float* Bptr = B + (size_t)(bn + lrow) * K + kq;

    float acc[8][4];
#pragma unroll
    for (int i = 0; i < 8; i++)
#pragma unroll
        for (int j = 0; j < 4; j++) acc[i][j] = 0.f;

    {
        float4 v0 = *(const float4*)(Aptr);
        float4 v1 = *(const float4*)(Aptr + (size_t)64 * K);
        float4 vb = *(const float4*)(Bptr);
        sA[0][kq + 0][lrow] = v0.x; sA[0][kq + 1][lrow] = v0.y;
        sA[0][kq + 2][lrow] = v0.z; sA[0][kq + 3][lrow] = v0.w;
        sA[0][kq + 0][lrow + 64] = v1.x; sA[0][kq + 1][lrow + 64] = v1.y;
        sA[0][kq + 2][lrow + 64] = v1.z; sA[0][kq + 3][lrow + 64] = v1.w;
        sB[0][kq + 0][lrow] = vb.x; sB[0][kq + 1][lrow] = vb.y;
        sB[0][kq + 2][lrow] = vb.z; sB[0][kq + 3][lrow] = vb.w;
    }
    __syncthreads();

    const int nk = K >> 4;
    for (int kt = 0; kt < nk; kt++) {
        const int cur = kt & 1;
        float4 v0, v1, vb;
        const bool pf = (kt + 1) < nk;
        if (pf) {
            const float* Ap = Aptr + ((kt + 1) << 4);
            v0 = *(const float4*)(Ap);
            v1 = *(const float4*)(Ap + (size_t)64 * K);
            vb = *(const float4*)(Bptr + ((kt + 1) << 4));
        }
#pragma unroll
        for (int kk = 0; kk < 16; kk++) {
            float a[8], b[4];
#pragma unroll
            for (int i = 0; i < 8; i++) a[i] = sA[cur][kk][ty + 16 * i];
#pragma unroll
            for (int j = 0; j < 4; j++) b[j] = sB[cur][kk][tx + 16 * j];
#pragma unroll
            for (int i = 0; i < 8; i++)
#pragma unroll
                for (int j = 0; j < 4; j++)
                    acc[i][j] = fmaf(a[i], b[j], acc[i][j]);
        }
        if (pf) {
            const int nb = cur ^ 1;
            sA[nb][kq + 0][lrow] = v0.x; sA[nb][kq + 1][lrow] = v0.y;
            sA[nb][kq + 2][lrow] = v0.z; sA[nb][kq + 3][lrow] = v0.w;
            sA[nb][kq + 0][lrow + 64] = v1.x; sA[nb][kq + 1][lrow + 64] = v1.y;
            sA[nb][kq + 2][lrow + 64] = v1.z; sA[nb][kq + 3][lrow + 64] = v1.w;
            sB[nb][kq + 0][lrow] = vb.x; sB[nb][kq + 1][lrow] = vb.y;
            sB[nb][kq + 2][lrow] = vb.z; sB[nb][kq + 3][lrow] = vb.w;
        }
        __syncthreads();
    }

    if (mode == 0) {
#pragma unroll
        for (int i = 0; i < 8; i++) {
            int row = bm + ty + 16 * i;
#pragma unroll
            for (int j = 0; j < 4; j++) {
                int col = bn + tx + 16 * j;
                C[(size_t)row * ldc + col] = acc[i][j] + bias[col];
            }
        }
    } else {
        // unit-blocked: memory [u*4 + gt] per row, u = col&511, gt = col>>9
#pragma unroll
        for (int i = 0; i < 8; i++) {
            int row = bm + ty + 16 * i;
#pragma unroll
            for (int j = 0; j < 4; j++) {
                int col = bn + tx + 16 * j;
                int dst = (col & 511) * 4 + (col >> 9);
                C[(size_t)row * 2048 + dst] = acc[i][j] + bias[col];
            }
        }
    }
}

// ---------------- char LSTM pointwise update ----------------
__global__ void char_pointwise(const int* __restrict__ chars,
                               const int* __restrict__ char_lens,
                               const float* __restrict__ char_embed, int t) {
    int idx = blockIdx.x * blockDim.x + threadIdx.x;
    if (idx < S_LEN * CHAR_HID) {
        int b = idx >> 7, j = idx & 127;
        const float* gr = g_gates + b * 512;
        float i_ = sigmoidf_(gr[j]);
        float f_ = sigmoidf_(gr[128 + j]);
        float gg = tanhf(gr[256 + j]);
        float o_ = sigmoidf_(gr[384 + j]);
        float c = f_ * g_c[idx] + i_ * gg;
        g_c[idx] = c;
        float h = o_ * tanhf(c);
        g_A[b * CK + CHAR_DIM + j] = h;               // input for next step
        if (char_lens[b] - 1 == t) g_cf[idx] = h;     // final char feature
    }
    if (t + 1 < L_CHARS && idx < S_LEN * CHAR_DIM) {
        int b = idx >> 6, k = idx & 63;
        g_A[b * CK + k] = char_embed[chars[b * L_CHARS + (t + 1)] * CHAR_DIM + k];
    }
}

// ---------------- word feature gather ----------------
__global__ void feats_kernel(const int* __restrict__ x,
                             const float* __restrict__ word_embed) {
    int i = blockIdx.x * blockDim.x + threadIdx.x;
    if (i < S_LEN * WK) {
        int s = i / WK, k = i - s * WK;
        g_F[i] = (k < WORD_DIM) ? word_embed[x[s] * WORD_DIM + k]
                                : g_cf[s * CHAR_HID + (k - WORD_DIM)];
    }
}

// ---------------- persistent word LSTM recurrence ----------------
// GW2=64 CTAs x 8 warps, warp <-> hidden unit (R10 skeleton, proven).
// SENTINEL-IN-PADDED-LINES sync: producer CTA j's 8 h values live alone in
// 128B line j (sentinel-poisoned); threads tid<64 poll chunk tid volatile
// and on detect already hold the data -> STS, one bar.
// NEW vs R10 (compute shrink):
//  * packed f32x2 FMA (FFMA2): lane covers col pairs {2l+64i, 2l+64i+1},
//    32 FFMA2 instead of 64 FFMA -> FMA issue/SMSP halves (~128cy)
//  * LDS.64 paired h reads (8x8B, conflict-free) instead of 16 scalar LDS
//  * parallel activations: lanes 0-3 each own one gate's wg scalar and
//    MUFU-activate their gate concurrently (4 serial chains -> 1, +shfl)
__global__ void __launch_bounds__(TPB2) word_lstm_kernel(const float* __restrict__ Whh) {
    __shared__ float sbuf[2][512];        // double-buffered dense h row

    const int cta = blockIdx.x;
    const int tid = threadIdx.x;
    const int w = tid >> 5;               // local unit 0..7
    const int lane = tid & 31;
    const int u = cta * 8 + w;            // global hidden unit 0..511

    // register-resident W_hh, paired: w2[gt][i] = W[gt*512+u][2*lane + 64*i .. +1]
    float2 w2[4][8];
#pragma unroll
    for (int gt = 0; gt < 4; gt++) {
        const float* p = Whh + (size_t)(gt * 512 + u) * 512 + 2 * lane;
#pragma unroll
        for (int i = 0; i < 8; i++) w2[gt][i] = *(const float2*)(p + 64 * i);
    }

    const bool l0 = (lane == 0);
    float c = 0.f;
    // lanes 0..3 each own their gate's input-gate scalar stream
    float wg_c = 0.f, wg_n = 0.f;
    if (lane < 4) {
        wg_c = g_wg[(size_t)0 * 2048 + u * 4 + lane];
        wg_n = g_wg[(size_t)1 * 2048 + u * 4 + lane];
    }

    for (int s = 0; s < S_LEN; s++) {
        // prefetch input gate two steps ahead (hidden under the wait)
        float wg_p = 0.f;
        if (lane < 4 && s + 2 < S_LEN) {
            asm volatile("ld.global.cg.f32 %0, [%1];"
                         : "=f"(wg_p)
                         : "l"(g_wg + (size_t)(s + 2) * 2048 + u * 4 + lane)
                         : "memory");
        }

        // threads 0..63: poll chunk tid of padded row s (data IS the signal)
        if (tid < 64) {
            const float* cp = g_hp + (size_t)s * HP_STRIDE + tid * 32;
            uint4 a, b;
            do {
                a = ldvol_u4(cp + 0);
                b = ldvol_u4(cp + 4);
            } while (any_sent_u(a) | any_sent_u(b));
            float4* d = (float4*)&sbuf[s & 1][tid * 8];
            d[0] = make_float4(__uint_as_float(a.x), __uint_as_float(a.y),
                               __uint_as_float(a.z), __uint_as_float(a.w));
            d[1] = make_float4(__uint_as_float(b.x), __uint_as_float(b.y),
                               __uint_as_float(b.z), __uint_as_float(b.w));
        }
        __syncthreads();                  // h[s] staged in smem

        // paired conflict-free h reads + packed FFMA2
        const float* hrow = sbuf[s & 1];
        float2 acc2[4];
#pragma unroll
        for (int gt = 0; gt < 4; gt++) acc2[gt] = make_float2(0.f, 0.f);
#pragma unroll
        for (int i = 0; i < 8; i++) {
            float2 h2 = *(const float2*)&hrow[2 * lane + 64 * i];
#pragma unroll
            for (int gt = 0; gt < 4; gt++)
                acc2[gt] = fma2_(w2[gt][i], h2, acc2[gt]);
        }
        float a0 = acc2[0].x + acc2[0].y;
        float a1 = acc2[1].x + acc2[1].y;
        float a2 = acc2[2].x + acc2[2].y;
        float a3 = acc2[3].x + acc2[3].y;

        // full-warp butterfly reduce (4 values)
#pragma unroll
        for (int off = 16; off > 0; off >>= 1) {
            a0 += __shfl_xor_sync(0xffffffffu, a0, off);
            a1 += __shfl_xor_sync(0xffffffffu, a1, off);
            a2 += __shfl_xor_sync(0xffffffffu, a2, off);
            a3 += __shfl_xor_sync(0xffffffffu, a3, off);
        }

        // parallel activations on lanes 0..3 (gate lane == gate index)
        float act = 0.f;
        if (lane < 4) {
            float v = (lane == 0 ? a0 : lane == 1 ? a1 : lane == 2 ? a2 : a3)
                      + wg_c;
            act = (lane == 2) ? tanh_acc(v) : sig_acc(v);
        }
        float i_ = __shfl_sync(0xffffffffu, act, 0);
        float f_ = __shfl_sync(0xffffffffu, act, 1);
        float g_ = __shfl_sync(0xffffffffu, act, 2);
        float o_ = __shfl_sync(0xffffffffu, act, 3);

        if (l0) {
            c = f_ * c + i_ * g_;
            float h = o_ * tanh_acc(c);   // finite, never NaN == sentinel-safe
            // publish into this CTA's own padded line (the poll target)...
            asm volatile("st.volatile.global.b32 [%0], %1;"
                         :: "l"(g_hp + (size_t)(s + 1) * HP_STRIDE + cta * 32 + w),
                            "r"(__float_as_uint(h)) : "memory");
            // ...and a dense copy for the classifier (off the critical path)
            asm volatile("st.global.cg.f32 [%0], %1;"
                         :: "l"(g_hd + (size_t)(s + 1) * 512 + u), "f"(h) : "memory");
        }
        wg_c = wg_n;
        wg_n = wg_p;
    }
}

// ---------------- host launch ----------------
extern "C" void kernel_launch(void* const* d_in, const int* in_sizes, int n_in,
                              void* d_out, int out_size) {
    (void)in_sizes; (void)n_in; (void)out_size;
    const int*   x          = (const int*)d_in[0];
    const int*   chars      = (const int*)d_in[1];
    const int*   char_lens  = (const int*)d_in[2];
    const float* word_embed = (const float*)d_in[3];
    const float* char_embed = (const float*)d_in[4];
    const float* c_Wih      = (const float*)d_in[5];
    const float* c_Whh      = (const float*)d_in[6];
    const float* c_bih      = (const float*)d_in[7];
    const float* c_bhh      = (const float*)d_in[8];
    const float* w_Wih      = (const float*)d_in[9];
    const float* w_Whh      = (const float*)d_in[10];
    const float* w_bih      = (const float*)d_in[11];
    const float* w_bhh      = (const float*)d_in[12];
    const float* cls_W      = (const float*)d_in[13];
    const float* cls_b      = (const float*)d_in[14];
    float* out = (float*)d_out;

    float *pA, *pWc, *pbc, *pgates, *pbw, *pF, *pwg, *phd;
    cudaGetSymbolAddress((void**)&pA,     g_A);
    cudaGetSymbolAddress((void**)&pWc,    g_Wc);
    cudaGetSymbolAddress((void**)&pbc,    g_bc);
    cudaGetSymbolAddress((void**)&pgates, g_gates);
    cudaGetSymbolAddress((void**)&pbw,    g_bw);
    cudaGetSymbolAddress((void**)&pF,     g_F);
    cudaGetSymbolAddress((void**)&pwg,    g_wg);
    cudaGetSymbolAddress((void**)&phd,    g_hd);

    prep_kernel<<<1024, 256>>>(chars, char_embed, c_Wih, c_Whh,
                               c_bih, c_bhh, w_bih, w_bhh);

    // char LSTM: 16 x (gates GEMM + pointwise)
    for (int t = 0; t < L_CHARS; t++) {
        gemm_bias<<<dim3(S_LEN / 128, 512 / 64), 256>>>(
            pA, pWc, pbc, pgates, CK, 512, 0);
        char_pointwise<<<(S_LEN * CHAR_HID) / 256, 256>>>(
            chars, char_lens, char_embed, t);
    }

    // word features + input-gate precompute (unit-blocked, biases folded)
    feats_kernel<<<(S_LEN * WK + 255) / 256, 256>>>(x, word_embed);
    gemm_bias<<<dim3(S_LEN / 128, 2048 / 64), 256>>>(
        pF, w_Wih, pbw, pwg, WK, 2048, 1);

    // sequential word LSTM (persistent, sentinel-in-padded-lines dataflow)
    word_lstm_kernel<<<GW2, TPB2>>>(w_Whh);

    // classifier: out = h_all @ cls_W^T + cls_b  (dense h, offset one row)
    gemm_bias<<<dim3(S_LEN / 128, 1), 256>>>(
        phd + 512, cls_W, cls_b, out, 512, N_TAG, 0);
}

// round 12
// speedup vs baseline: 1.1396x; 1.1396x over previous
#include <cuda_runtime.h>
#include <cuda_bf16.h>
#include <math.h>

// ---------------- problem constants ----------------
#define S_LEN   8192
#define L_CHARS 16
#define CHAR_DIM 64
#define WORD_DIM 256
#define CHAR_HID 128
#define WORD_HID 512
#define N_TAG   64
#define CK      192              // CHAR_DIM + CHAR_HID (char gemm K)
#define WK      384              // WORD_DIM + CHAR_HID (word input gemm K)
#define GW2     128              // persistent CTAs for word LSTM (1/SM, <=148)
#define TPB2    128              // 4 warps = 4 hidden units per CTA (1 warp/SMSP)
#define SENT    0x7fbadbadu     // NaN-pattern sentinel (h can never be NaN)
#define HP_STRIDE 4096           // padded h row: 128 chunks x 32 floats (128B lines)

// ---------------- device scratch (no cudaMalloc allowed) ----------------
__device__ __align__(16) float g_A[S_LEN * CK];        // char gemm input [ce_t | h]
__device__ __align__(16) float g_gates[S_LEN * 512];   // char gates
__device__ __align__(16) float g_c[S_LEN * CHAR_HID];  // char cell state
__device__ __align__(16) float g_cf[S_LEN * CHAR_HID]; // char features
__device__ __align__(16) float g_Wc[512 * CK];         // concat [c_Wih | c_Whh]
__device__ __align__(16) float g_bc[512];              // c_bih + c_bhh
__device__ __align__(16) float g_bw[2048];             // w_bih + w_bhh
__device__ __align__(16) float g_F[S_LEN * WK];        // word feats [we | cf]
__device__ __align__(16) float g_wg[S_LEN * 2048];     // word input gates (unit f4)
__device__ __align__(16) float g_hp[(S_LEN + 1) * HP_STRIDE]; // padded h (poll target)
__device__ __align__(16) float g_hd[(S_LEN + 1) * 512];       // dense h (classifier)

__device__ __forceinline__ float sigmoidf_(float x) { return 1.f / (1.f + expf(-x)); }

// Accurate fast activations (2-ulp MUFU exp + fast divide).
// tanh.approx.f32 (5e-4 abs err) amplifies ~600x through the 8192-step
// recurrence -> 0.316 rel_err (R4). These stay at ~1e-7 per step.
__device__ __forceinline__ float sig_acc(float x) {
    x = fminf(fmaxf(x, -30.f), 30.f);
    float e = __expf(-x);
    return __fdividef(1.f, 1.f + e);
}
__device__ __forceinline__ float tanh_acc(float x) {
    x = fminf(fmaxf(x, -15.f), 15.f);
    float e = __expf(2.f * x);
    return __fdividef(e - 1.f, e + 1.f);
}
__device__ __forceinline__ float4 ldcg_f4(const float* p) {
    float4 v;
    asm volatile("ld.global.cg.v4.f32 {%0,%1,%2,%3}, [%4];"
                 : "=f"(v.x), "=f"(v.y), "=f"(v.z), "=f"(v.w) : "l"(p) : "memory");
    return v;
}
// VOLATILE poll load (ptxas may legally hoist weak loads out of spin loops --
// the R6 failure). Integer regs: no float compare on the NaN sentinel.
__device__ __forceinline__ uint4 ldvol_u4(const float* p) {
    uint4 v;
    asm volatile("ld.volatile.global.v4.b32 {%0,%1,%2,%3}, [%4];"
                 : "=r"(v.x), "=r"(v.y), "=r"(v.z), "=r"(v.w) : "l"(p) : "memory");
    return v;
}
__device__ __forceinline__ unsigned any_sent_u(uint4 v) {
    return (unsigned)(v.x == SENT) | (unsigned)(v.y == SENT) |
           (unsigned)(v.z == SENT) | (unsigned)(v.w == SENT);
}

// ---------------- prep: concat weights, biases, init buffers ----------------
__global__ void prep_kernel(const int* __restrict__ chars,
                            const float* __restrict__ char_embed,
                            const float* __restrict__ c_Wih,
                            const float* __restrict__ c_Whh,
                            const float* __restrict__ c_bih,
                            const float* __restrict__ c_bhh,
                            const float* __restrict__ w_bih,
                            const float* __restrict__ w_bhh) {
    int tid = blockIdx.x * blockDim.x + threadIdx.x;
    int stride = gridDim.x * blockDim.x;
    for (int i = tid; i < 512 * CK; i += stride) {
        int j = i / CK, k = i - j * CK;
        g_Wc[i] = (k < CHAR_DIM) ? c_Wih[j * CHAR_DIM + k]
                                 : c_Whh[j * CHAR_HID + (k - CHAR_DIM)];
    }
    for (int i = tid; i < 512; i += stride) g_bc[i] = c_bih[i] + c_bhh[i];
    for (int i = tid; i < 2048; i += stride) g_bw[i] = w_bih[i] + w_bhh[i];
    for (int i = tid; i < S_LEN * CHAR_HID; i += stride) g_c[i] = 0.f;
    // padded h: row 0 = zeros (initial state), rows 1..S = sentinel
    // (re-poisoned on every launch / graph replay)
    for (int i = tid; i < (S_LEN + 1) * HP_STRIDE; i += stride)
        ((unsigned*)g_hp)[i] = (i < HP_STRIDE) ? 0u : SENT;
    for (int i = tid; i < 512; i += stride) g_hd[i] = 0.f;  // dense row 0
    // char gemm input for t=0: ce in cols [0,64), zeros (h0) in [64,192)
    for (int i = tid; i < S_LEN * CK; i += stride) {
        int b = i / CK, k = i - b * CK;
        g_A[i] = (k < CHAR_DIM)
                   ? char_embed[chars[b * L_CHARS + 0] * CHAR_DIM + k]
                   : 0.f;
    }
}

// ---------------- generic fp32 GEMM: C = A(MxK) * B(NxK)^T + bias ----------------
// BM=128 BN=64 BK=16, 256 threads, 8x4 per-thread tile.
// mode 0: C[row*ldc+col] = acc + bias[col]
// mode 1: word-gate unit-blocked store: dst = (col&511)*4 + (col>>9)
__global__ void __launch_bounds__(256) gemm_bias(const float* __restrict__ A,
                                                 const float* __restrict__ B,
                                                 const float* __restrict__ bias,
                                                 float* __restrict__ C,
                                                 int K, int ldc, int mode) {
    __shared__ float sA[2][16][129];
    __shared__ float sB[2][16][65];
    const int bm = blockIdx.x << 7;
    const int bn = blockIdx.y << 6;
    const int tid = threadIdx.x;
    const int tx = tid & 15;
    const int ty = tid >> 4;
    const int lrow = tid >> 2;
    const int kq = (tid & 3) << 2;

    const float* Aptr = A + (size_t)(bm + lrow) * K + kq;
    const float* Bptr = B + (size_t)(bn + lrow) * K + kq;

    float acc[8][4];
#pragma unroll
    for (int i = 0; i < 8; i++)
#pragma unroll
        for (int j = 0; j < 4; j++) acc[i][j] = 0.f;

    {
        float4 v0 = *(const float4*)(Aptr);
        float4 v1 = *(const float4*)(Aptr + (size_t)64 * K);
        float4 vb = *(const float4*)(Bptr);
        sA[0][kq + 0][lrow] = v0.x; sA[0][kq + 1][lrow] = v0.y;
        sA[0][kq + 2][lrow] = v0.z; sA[0][kq + 3][lrow] = v0.w;
        sA[0][kq + 0][lrow + 64] = v1.x; sA[0][kq + 1][lrow + 64] = v1.y;
        sA[0][kq + 2][lrow + 64] = v1.z; sA[0][kq + 3][lrow + 64] = v1.w;
        sB[0][kq + 0][lrow] = vb.x; sB[0][kq + 1][lrow] = vb.y;
        sB[0][kq + 2][lrow] = vb.z; sB[0][kq + 3][lrow] = vb.w;
    }
    __syncthreads();

    const int nk = K >> 4;
    for (int kt = 0; kt < nk; kt++) {
        const int cur = kt & 1;
        float4 v0, v1, vb;
        const bool pf = (kt + 1) < nk;
        if (pf) {
            const float* Ap = Aptr + ((kt + 1) << 4);
            v0 = *(const float4*)(Ap);
            v1 = *(const float4*)(Ap + (size_t)64 * K);
            vb = *(const float4*)(Bptr + ((kt + 1) << 4));
        }
#pragma unroll
        for (int kk = 0; kk < 16; kk++) {
            float a[8], b[4];
#pragma unroll
            for (int i = 0; i < 8; i++) a[i] = sA[cur][kk][ty + 16 * i];
#pragma unroll
            for (int j = 0; j < 4; j++) b[j] = sB[cur][kk][tx + 16 * j];
#pragma unroll
            for (int i = 0; i < 8; i++)
#pragma unroll
                for (int j = 0; j < 4; j++)
                    acc[i][j] = fmaf(a[i], b[j], acc[i][j]);
        }
        if (pf) {
            const int nb = cur ^ 1;
            sA[nb][kq + 0][lrow] = v0.x; sA[nb][kq + 1][lrow] = v0.y;
            sA[nb][kq + 2][lrow] = v0.z; sA[nb][kq + 3][lrow] = v0.w;
            sA[nb][kq + 0][lrow + 64] = v1.x; sA[nb][kq + 1][lrow + 64] = v1.y;
            sA[nb][kq + 2][lrow + 64] = v1.z; sA[nb][kq + 3][lrow + 64] = v1.w;
            sB[nb][kq + 0][lrow] = vb.x; sB[nb][kq + 1][lrow] = vb.y;
            sB[nb][kq + 2][lrow] = vb.z; sB[nb][kq + 3][lrow] = vb.w;
        }
        __syncthreads();
    }

    if (mode == 0) {
#pragma unroll
        for (int i = 0; i < 8; i++) {
            int row = bm + ty + 16 * i;
#pragma unroll
            for (int j = 0; j < 4; j++) {
                int col = bn + tx + 16 * j;
                C[(size_t)row * ldc + col] = acc[i][j] + bias[col];
            }
        }
    } else {
        // unit-blocked: memory [u*4 + gt] per row, u = col&511, gt = col>>9
#pragma unroll
        for (int i = 0; i < 8; i++) {
            int row = bm + ty + 16 * i;
#pragma unroll
            for (int j = 0; j < 4; j++) {
                int col = bn + tx + 16 * j;
                int dst = (col & 511) * 4 + (col >> 9);
                C[(size_t)row * 2048 + dst] = acc[i][j] + bias[col];
            }
        }
    }
}

// ---------------- char LSTM pointwise update ----------------
__global__ void char_pointwise(const int* __restrict__ chars,
                               const int* __restrict__ char_lens,
                               const float* __restrict__ char_embed, int t) {
    int idx = blockIdx.x * blockDim.x + threadIdx.x;
    if (idx < S_LEN * CHAR_HID) {
        int b = idx >> 7, j = idx & 127;
        const float* gr = g_gates + b * 512;
        float i_ = sigmoidf_(gr[j]);
        float f_ = sigmoidf_(gr[128 + j]);
        float gg = tanhf(gr[256 + j]);
        float o_ = sigmoidf_(gr[384 + j]);
        float c = f_ * g_c[idx] + i_ * gg;
        g_c[idx] = c;
        float h = o_ * tanhf(c);
        g_A[b * CK + CHAR_DIM + j] = h;               // input for next step
        if (char_lens[b] - 1 == t) g_cf[idx] = h;     // final char feature
    }
    if (t + 1 < L_CHARS && idx < S_LEN * CHAR_DIM) {
        int b = idx >> 6, k = idx & 63;
        g_A[b * CK + k] = char_embed[chars[b * L_CHARS + (t + 1)] * CHAR_DIM + k];
    }
}

// ---------------- word feature gather ----------------
__global__ void feats_kernel(const int* __restrict__ x,
                             const float* __restrict__ word_embed) {
    int i = blockIdx.x * blockDim.x + threadIdx.x;
    if (i < S_LEN * WK) {
        int s = i / WK, k = i - s * WK;
        g_F[i] = (k < WORD_DIM) ? word_embed[x[s] * WORD_DIM + k]
                                : g_cf[s * CHAR_HID + (k - WORD_DIM)];
    }
}

// ---------------- persistent word LSTM recurrence ----------------
// GW2=128 CTAs x 4 warps, warp <-> hidden unit (512 warps = 512 units).
// ONE compute warp per SMSP -> no issue contention -> the CTA's slowest
// warp (which gates its chunk's completeness) publishes ~250-400cy earlier
// than the R10 8-warp layout. SENTINEL-IN-PADDED-LINES sync unchanged:
// producer CTA j's 4 h values live alone in 128B line j (poisoned);
// every thread polls chunk tid with ONE ld.volatile.v4 (shorter round
// than R10's double load) and on detect already holds the data -> STS,
// one bar. Line j is polled by exactly one thread per CTA (128/line).
// Compute identical to R10 (measured faster than the R11 FFMA2 variant).
__global__ void __launch_bounds__(TPB2) word_lstm_kernel(const float* __restrict__ Whh) {
    __shared__ float sbuf[2][512];        // double-buffered dense h row

    const int cta = blockIdx.x;
    const int tid = threadIdx.x;
    const int w = tid >> 5;               // local unit 0..3
    const int lane = tid & 31;
    const int u = cta * 4 + w;            // global hidden unit 0..511

    // register-resident W_hh: wreg[gt][i] = Whh[(gt*512+u)*512 + i*32 + lane]
    float wreg[4][16];
#pragma unroll
    for (int gt = 0; gt < 4; gt++) {
        const float* p = Whh + (size_t)(gt * 512 + u) * 512 + lane;
#pragma unroll
        for (int i = 0; i < 16; i++) wreg[gt][i] = p[i * 32];
    }

    const bool l0 = (lane == 0);
    float c = 0.f;
    float4 wg_cur = make_float4(0.f, 0.f, 0.f, 0.f);
    float4 wg_nxt = wg_cur;
    if (l0) {
        wg_cur = *(const float4*)(g_wg + (size_t)0 * 2048 + u * 4);
        wg_nxt = *(const float4*)(g_wg + (size_t)1 * 2048 + u * 4);
    }

    for (int s = 0; s < S_LEN; s++) {
        // prefetch input gates two steps ahead (hidden under the wait)
        float4 wg_pf = make_float4(0.f, 0.f, 0.f, 0.f);
        if (l0 && s + 2 < S_LEN)
            wg_pf = ldcg_f4(g_wg + (size_t)(s + 2) * 2048 + u * 4);

        // every thread polls chunk tid of padded row s (data IS the signal)
        {
            const float* cp = g_hp + (size_t)s * HP_STRIDE + tid * 32;
            uint4 a;
            do {
                a = ldvol_u4(cp);
            } while (any_sent_u(a));
            *(float4*)&sbuf[s & 1][tid * 4] =
                make_float4(__uint_as_float(a.x), __uint_as_float(a.y),
                            __uint_as_float(a.z), __uint_as_float(a.w));
        }
        __syncthreads();                  // h[s] staged in smem

        // conflict-free stride-32 h read
        const float* hrow = sbuf[s & 1];
        float hv[16];
#pragma unroll
        for (int i = 0; i < 16; i++) hv[i] = hrow[i * 32 + lane];

        float a0 = 0.f, a1 = 0.f, a2 = 0.f, a3 = 0.f;
#pragma unroll
        for (int i = 0; i < 16; i++) {
            a0 = fmaf(wreg[0][i], hv[i], a0);
            a1 = fmaf(wreg[1][i], hv[i], a1);
            a2 = fmaf(wreg[2][i], hv[i], a2);
            a3 = fmaf(wreg[3][i], hv[i], a3);
        }

        // full-warp butterfly reduce (4 values)
#pragma unroll
        for (int off = 16; off > 0; off >>= 1) {
            a0 += __shfl_xor_sync(0xffffffffu, a0, off);
            a1 += __shfl_xor_sync(0xffffffffu, a1, off);
            a2 += __shfl_xor_sync(0xffffffffu, a2, off);
            a3 += __shfl_xor_sync(0xffffffffu, a3, off);
        }

        if (l0) {
            float i_ = sig_acc(a0 + wg_cur.x);
            float f_ = sig_acc(a1 + wg_cur.y);
            float g_ = tanh_acc(a2 + wg_cur.z);
            float o_ = sig_acc(a3 + wg_cur.w);
            c = f_ * c + i_ * g_;
            float h = o_ * tanh_acc(c);   // finite, never NaN == sentinel-safe
            // publish into this CTA's own padded line (the poll target)...
            asm volatile("st.volatile.global.b32 [%0], %1;"
                         :: "l"(g_hp + (size_t)(s + 1) * HP_STRIDE + cta * 32 + w),
                            "r"(__float_as_uint(h)) : "memory");
            // ...and a dense copy for the classifier (off the critical path)
            asm volatile("st.global.cg.f32 [%0], %1;"
                         :: "l"(g_hd + (size_t)(s + 1) * 512 + u), "f"(h) : "memory");
            wg_cur = wg_nxt;
            wg_nxt = wg_pf;
        }
    }
}

// ---------------- host launch ----------------
extern "C" void kernel_launch(void* const* d_in, const int* in_sizes, int n_in,
                              void* d_out, int out_size) {
    (void)in_sizes; (void)n_in; (void)out_size;
    const int*   x          = (const int*)d_in[0];
    const int*   chars      = (const int*)d_in[1];
    const int*   char_lens  = (const int*)d_in[2];
    const float* word_embed = (const float*)d_in[3];
    const float* char_embed = (const float*)d_in[4];
    const float* c_Wih      = (const float*)d_in[5];
    const float* c_Whh      = (const float*)d_in[6];
    const float* c_bih      = (const float*)d_in[7];
    const float* c_bhh      = (const float*)d_in[8];
    const float* w_Wih      = (const float*)d_in[9];
    const float* w_Whh      = (const float*)d_in[10];
    const float* w_bih      = (const float*)d_in[11];
    const float* w_bhh      = (const float*)d_in[12];
    const float* cls_W      = (const float*)d_in[13];
    const float* cls_b      = (const float*)d_in[14];
    float* out = (float*)d_out;

    float *pA, *pWc, *pbc, *pgates, *pbw, *pF, *pwg, *phd;
    cudaGetSymbolAddress((void**)&pA,     g_A);
    cudaGetSymbolAddress((void**)&pWc,    g_Wc);
    cudaGetSymbolAddress((void**)&pbc,    g_bc);
    cudaGetSymbolAddress((void**)&pgates, g_gates);
    cudaGetSymbolAddress((void**)&pbw,    g_bw);
    cudaGetSymbolAddress((void**)&pF,     g_F);
    cudaGetSymbolAddress((void**)&pwg,    g_wg);
    cudaGetSymbolAddress((void**)&phd,    g_hd);

    prep_kernel<<<1024, 256>>>(chars, char_embed, c_Wih, c_Whh,
                               c_bih, c_bhh, w_bih, w_bhh);

    // char LSTM: 16 x (gates GEMM + pointwise)
    for (int t = 0; t < L_CHARS; t++) {
        gemm_bias<<<dim3(S_LEN / 128, 512 / 64), 256>>>(
            pA, pWc, pbc, pgates, CK, 512, 0);
        char_pointwise<<<(S_LEN * CHAR_HID) / 256, 256>>>(
            chars, char_lens, char_embed, t);
    }

    // word features + input-gate precompute (unit-blocked, biases folded)
    feats_kernel<<<(S_LEN * WK + 255) / 256, 256>>>(x, word_embed);
    gemm_bias<<<dim3(S_LEN / 128, 2048 / 64), 256>>>(
        pF, w_Wih, pbw, pwg, WK, 2048, 1);

    // sequential word LSTM (persistent, sentinel-in-padded-lines dataflow)
    word_lstm_kernel<<<GW2, TPB2>>>(w_Whh);

    // classifier: out = h_all @ cls_W^T + cls_b  (dense h, offset one row)
    gemm_bias<<<dim3(S_LEN / 128, 1), 256>>>(
        phd + 512, cls_W, cls_b, out, 512, N_TAG, 0);
}

// round 13
// speedup vs baseline: 1.1437x; 1.0036x over previous
#include <cuda_runtime.h>
#include <cuda_bf16.h>
#include <math.h>

// ---------------- problem constants ----------------
#define S_LEN   8192
#define L_CHARS 16
#define CHAR_DIM 64
#define WORD_DIM 256
#define CHAR_HID 128
#define WORD_HID 512
#define N_TAG   64
#define CK      192              // CHAR_DIM + CHAR_HID (char gemm K)
#define WK      384              // WORD_DIM + CHAR_HID (word input gemm K)
#define GW2     128              // persistent CTAs for word LSTM (1/SM, <=148)
#define TPB2    128              // 4 warps = 4 hidden units per CTA (1 warp/SMSP)
#define SENT    0x7fbadbadu     // NaN-pattern sentinel (h can never be NaN)
#define NREP    4                // publish-line replicas (readers/line: 128 -> 32)
#define REP_STRIDE 4096          // floats per replica (128 chunks x 32)
#define HP_STRIDE (NREP * REP_STRIDE)   // padded h row: 16384 floats

// ---------------- device scratch (no cudaMalloc allowed) ----------------
__device__ __align__(16) float g_A[S_LEN * CK];        // char gemm input [ce_t | h]
__device__ __align__(16) float g_gates[S_LEN * 512];   // char gates
__device__ __align__(16) float g_c[S_LEN * CHAR_HID];  // char cell state
__device__ __align__(16) float g_cf[S_LEN * CHAR_HID]; // char features
__device__ __align__(16) float g_Wc[512 * CK];         // concat [c_Wih | c_Whh]
__device__ __align__(16) float g_bc[512];              // c_bih + c_bhh
__device__ __align__(16) float g_bw[2048];             // w_bih + w_bhh
__device__ __align__(16) float g_F[S_LEN * WK];        // word feats [we | cf]
__device__ __align__(16) float g_wg[S_LEN * 2048];     // word input gates (unit f4)
__device__ __align__(16) float g_hp[(size_t)(S_LEN + 1) * HP_STRIDE]; // replicated h
__device__ __align__(16) float g_hd[(S_LEN + 1) * 512];               // dense h

__device__ __forceinline__ float sigmoidf_(float x) { return 1.f / (1.f + expf(-x)); }

// Accurate fast activations (2-ulp MUFU exp + fast divide).
// tanh.approx.f32 (5e-4 abs err) amplifies ~600x through the 8192-step
// recurrence -> 0.316 rel_err (R4). These stay at ~1e-7 per step.
__device__ __forceinline__ float sig_acc(float x) {
    x = fminf(fmaxf(x, -30.f), 30.f);
    float e = __expf(-x);
    return __fdividef(1.f, 1.f + e);
}
__device__ __forceinline__ float tanh_acc(float x) {
    x = fminf(fmaxf(x, -15.f), 15.f);
    float e = __expf(2.f * x);
    return __fdividef(e - 1.f, e + 1.f);
}
__device__ __forceinline__ float4 ldcg_f4(const float* p) {
    float4 v;
    asm volatile("ld.global.cg.v4.f32 {%0,%1,%2,%3}, [%4];"
                 : "=f"(v.x), "=f"(v.y), "=f"(v.z), "=f"(v.w) : "l"(p) : "memory");
    return v;
}
// VOLATILE poll load (ptxas may legally hoist weak loads out of spin loops --
// the R6 failure). Integer regs: no float compare on the NaN sentinel.
__device__ __forceinline__ uint4 ldvol_u4(const float* p) {
    uint4 v;
    asm volatile("ld.volatile.global.v4.b32 {%0,%1,%2,%3}, [%4];"
                 : "=r"(v.x), "=r"(v.y), "=r"(v.z), "=r"(v.w) : "l"(p) : "memory");
    return v;
}
__device__ __forceinline__ unsigned any_sent_u(uint4 v) {
    return (unsigned)(v.x == SENT) | (unsigned)(v.y == SENT) |
           (unsigned)(v.z == SENT) | (unsigned)(v.w == SENT);
}

// ---------------- prep: concat weights, biases, init buffers ----------------
__global__ void prep_kernel(const int* __restrict__ chars,
                            const float* __restrict__ char_embed,
                            const float* __restrict__ c_Wih,
                            const float* __restrict__ c_Whh,
                            const float* __restrict__ c_bih,
                            const float* __restrict__ c_bhh,
                            const float* __restrict__ w_bih,
                            const float* __restrict__ w_bhh) {
    size_t tid = blockIdx.x * blockDim.x + threadIdx.x;
    size_t stride = (size_t)gridDim.x * blockDim.x;
    for (size_t i = tid; i < 512 * CK; i += stride) {
        int j = (int)(i / CK), k = (int)(i - (size_t)j * CK);
        g_Wc[i] = (k < CHAR_DIM) ? c_Wih[j * CHAR_DIM + k]
                                 : c_Whh[j * CHAR_HID + (k - CHAR_DIM)];
    }
    for (size_t i = tid; i < 512; i += stride) g_bc[i] = c_bih[i] + c_bhh[i];
    for (size_t i = tid; i < 2048; i += stride) g_bw[i] = w_bih[i] + w_bhh[i];
    for (size_t i = tid; i < S_LEN * CHAR_HID; i += stride) g_c[i] = 0.f;
    // replicated h: row 0 = zeros in ALL replicas, rows 1..S = sentinel
    // (re-poisoned on every launch / graph replay)
    for (size_t i = tid; i < (size_t)(S_LEN + 1) * HP_STRIDE; i += stride)
        ((unsigned*)g_hp)[i] = (i < HP_STRIDE) ? 0u : SENT;
    for (size_t i = tid; i < 512; i += stride) g_hd[i] = 0.f;  // dense row 0
    // char gemm input for t=0: ce in cols [0,64), zeros (h0) in [64,192)
    for (size_t i = tid; i < S_LEN * CK; i += stride) {
        int b = (int)(i / CK), k = (int)(i - (size_t)b * CK);
        g_A[i] = (k < CHAR_DIM)
                   ? char_embed[chars[b * L_CHARS + 0] * CHAR_DIM + k]
                   : 0.f;
    }
}

// ---------------- generic fp32 GEMM: C = A(MxK) * B(NxK)^T + bias ----------------
// BM=128 BN=64 BK=16, 256 threads, 8x4 per-thread tile.
// mode 0: C[row*ldc+col] = acc + bias[col]
// mode 1: word-gate unit-blocked store: dst = (col&511)*4 + (col>>9)
__global__ void __launch_bounds__(256) gemm_bias(const float* __restrict__ A,
                                                 const float* __restrict__ B,
                                                 const float* __restrict__ bias,
                                                 float* __restrict__ C,
                                                 int K, int ldc, int mode) {
    __shared__ float sA[2][16][129];
    __shared__ float sB[2][16][65];
    const int bm = blockIdx.x << 7;
    const int bn = blockIdx.y << 6;
    const int tid = threadIdx.x;
    const int tx = tid & 15;
    const int ty = tid >> 4;
    const int lrow = tid >> 2;
    const int kq = (tid & 3) << 2;

    const float* Aptr = A + (size_t)(bm + lrow) * K + kq;
    const float* Bptr = B + (size_t)(bn + lrow) * K + kq;

    float acc[8][4];
#pragma unroll
    for (int i = 0; i < 8; i++)
#pragma unroll
        for (int j = 0; j < 4; j++) acc[i][j] = 0.f;

    {
        float4 v0 = *(const float4*)(Aptr);
        float4 v1 = *(const float4*)(Aptr + (size_t)64 * K);
        float4 vb = *(const float4*)(Bptr);
        sA[0][kq + 0][lrow] = v0.x; sA[0][kq + 1][lrow] = v0.y;
        sA[0][kq + 2][lrow] = v0.z; sA[0][kq + 3][lrow] = v0.w;
        sA[0][kq + 0][lrow + 64] = v1.x; sA[0][kq + 1][lrow + 64] = v1.y;
        sA[0][kq + 2][lrow + 64] = v1.z; sA[0][kq + 3][lrow + 64] = v1.w;
        sB[0][kq + 0][lrow] = vb.x; sB[0][kq + 1][lrow] = vb.y;
        sB[0][kq + 2][lrow] = vb.z; sB[0][kq + 3][lrow] = vb.w;
    }
    __syncthreads();

    const int nk = K >> 4;
    for (int kt = 0; kt < nk; kt++) {
        const int cur = kt & 1;
        float4 v0, v1, vb;
        const bool pf = (kt + 1) < nk;
        if (pf) {
            const float* Ap = Aptr + ((kt + 1) << 4);
            v0 = *(const float4*)(Ap);
            v1 = *(const float4*)(Ap + (size_t)64 * K);
            vb = *(const float4*)(Bptr + ((kt + 1) << 4));
        }
#pragma unroll
        for (int kk = 0; kk < 16; kk++) {
            float a[8], b[4];
#pragma unroll
            for (int i = 0; i < 8; i++) a[i] = sA[cur][kk][ty + 16 * i];
#pragma unroll
            for (int j = 0; j < 4; j++) b[j] = sB[cur][kk][tx + 16 * j];
#pragma unroll
            for (int i = 0; i < 8; i++)
#pragma unroll
                for (int j = 0; j < 4; j++)
                    acc[i][j] = fmaf(a[i], b[j], acc[i][j]);
        }
        if (pf) {
            const int nb = cur ^ 1;
            sA[nb][kq + 0][lrow] = v0.x; sA[nb][kq + 1][lrow] = v0.y;
            sA[nb][kq + 2][lrow] = v0.z; sA[nb][kq + 3][lrow] = v0.w;
            sA[nb][kq + 0][lrow + 64] = v1.x; sA[nb][kq + 1][lrow + 64] = v1.y;
            sA[nb][kq + 2][lrow + 64] = v1.z; sA[nb][kq + 3][lrow + 64] = v1.w;
            sB[nb][kq + 0][lrow] = vb.x; sB[nb][kq + 1][lrow] = vb.y;
            sB[nb][kq + 2][lrow] = vb.z; sB[nb][kq + 3][lrow] = vb.w;
        }
        __syncthreads();
    }

    if (mode == 0) {
#pragma unroll
        for (int i = 0; i < 8; i++) {
            int row = bm + ty + 16 * i;
#pragma unroll
            for (int j = 0; j < 4; j++) {
                int col = bn + tx + 16 * j;
                C[(size_t)row * ldc + col] = acc[i][j] + bias[col];
            }
        }
    } else {
        // unit-blocked: memory [u*4 + gt] per row, u = col&511, gt = col>>9
#pragma unroll
        for (int i = 0; i < 8; i++) {
            int row = bm + ty + 16 * i;
#pragma unroll
            for (int j = 0; j < 4; j++) {
                int col = bn + tx + 16 * j;
                int dst = (col & 511) * 4 + (col >> 9);
                C[(size_t)row * 2048 + dst] = acc[i][j] + bias[col];
            }
        }
    }
}

// ---------------- char LSTM pointwise update ----------------
__global__ void char_pointwise(const int* __restrict__ chars,
                               const int* __restrict__ char_lens,
                               const float* __restrict__ char_embed, int t) {
    int idx = blockIdx.x * blockDim.x + threadIdx.x;
    if (idx < S_LEN * CHAR_HID) {
        int b = idx >> 7, j = idx & 127;
        const float* gr = g_gates + b * 512;
        float i_ = sigmoidf_(gr[j]);
        float f_ = sigmoidf_(gr[128 + j]);
        float gg = tanhf(gr[256 + j]);
        float o_ = sigmoidf_(gr[384 + j]);
        float c = f_ * g_c[idx] + i_ * gg;
        g_c[idx] = c;
        float h = o_ * tanhf(c);
        g_A[b * CK + CHAR_DIM + j] = h;               // input for next step
        if (char_lens[b] - 1 == t) g_cf[idx] = h;     // final char feature
    }
    if (t + 1 < L_CHARS && idx < S_LEN * CHAR_DIM) {
        int b = idx >> 6, k = idx & 63;
        g_A[b * CK + k] = char_embed[chars[b * L_CHARS + (t + 1)] * CHAR_DIM + k];
    }
}

// ---------------- word feature gather ----------------
__global__ void feats_kernel(const int* __restrict__ x,
                             const float* __restrict__ word_embed) {
    int i = blockIdx.x * blockDim.x + threadIdx.x;
    if (i < S_LEN * WK) {
        int s = i / WK, k = i - s * WK;
        g_F[i] = (k < WORD_DIM) ? word_embed[x[s] * WORD_DIM + k]
                                : g_cf[s * CHAR_HID + (k - WORD_DIM)];
    }
}

// ---------------- persistent word LSTM recurrence ----------------
// GW2=128 CTAs x 4 warps, warp <-> hidden unit (1 warp/SMSP; R12 layout).
// SENTINEL-IN-PADDED-LINES sync with 4x REPLICATION: producer CTA j's 4 h
// values are written into 4 replica lines (one per lane 0..3 -- all lanes
// redundantly compute the gates/c/h after the butterfly, so the stores are
// parallel and the arithmetic is bitwise identical across lanes). Consumer
// CTA c polls ONLY replica (c & 3): readers per 128B line drop 128 -> 32,
// shrinking the LTS read-queue the producer's store and the final detect
// read must drain through (the R12 bottleneck: ~128 near-synchronized
// reads/line/round at ~1 req/cy/slice). Lane 4 writes the dense copy.
__global__ void __launch_bounds__(TPB2) word_lstm_kernel(const float* __restrict__ Whh) {
    __shared__ float sbuf[2][512];        // double-buffered dense h row

    const int cta = blockIdx.x;
    const int tid = threadIdx.x;
    const int w = tid >> 5;               // local unit 0..3
    const int lane = tid & 31;
    const int u = cta * 4 + w;            // global hidden unit 0..511

    // register-resident W_hh: wreg[gt][i] = Whh[(gt*512+u)*512 + i*32 + lane]
    float wreg[4][16];
#pragma unroll
    for (int gt = 0; gt < 4; gt++) {
        const float* p = Whh + (size_t)(gt * 512 + u) * 512 + lane;
#pragma unroll
        for (int i = 0; i < 16; i++) wreg[gt][i] = p[i * 32];
    }

    float c = 0.f;
    // all lanes load the same wg float4 (coalesced broadcast) so every lane
    // can compute the gate activations and c/h redundantly
    float4 wg_cur = *(const float4*)(g_wg + (size_t)0 * 2048 + u * 4);
    float4 wg_nxt = *(const float4*)(g_wg + (size_t)1 * 2048 + u * 4);

    const size_t my_rep = (size_t)(cta & (NREP - 1)) * REP_STRIDE;

    for (int s = 0; s < S_LEN; s++) {
        // prefetch input gates two steps ahead (hidden under the wait)
        float4 wg_pf = make_float4(0.f, 0.f, 0.f, 0.f);
        if (s + 2 < S_LEN)
            wg_pf = ldcg_f4(g_wg + (size_t)(s + 2) * 2048 + u * 4);

        // every thread polls chunk tid of its replica (data IS the signal)
        {
            const float* cp = g_hp + (size_t)s * HP_STRIDE + my_rep + tid * 32;
            uint4 a;
            do {
                a = ldvol_u4(cp);
            } while (any_sent_u(a));
            *(float4*)&sbuf[s & 1][tid * 4] =
                make_float4(__uint_as_float(a.x), __uint_as_float(a.y),
                            __uint_as_float(a.z), __uint_as_float(a.w));
        }
        __syncthreads();                  // h[s] staged in smem

        // conflict-free stride-32 h read
        const float* hrow = sbuf[s & 1];
        float hv[16];
#pragma unroll
        for (int i = 0; i < 16; i++) hv[i] = hrow[i * 32 + lane];

        float a0 = 0.f, a1 = 0.f, a2 = 0.f, a3 = 0.f;
#pragma unroll
        for (int i = 0; i < 16; i++) {
            a0 = fmaf(wreg[0][i], hv[i], a0);
            a1 = fmaf(wreg[1][i], hv[i], a1);
            a2 = fmaf(wreg[2][i], hv[i], a2);
            a3 = fmaf(wreg[3][i], hv[i], a3);
        }

        // full-warp butterfly reduce (4 values) -> every lane holds a0..a3
#pragma unroll
        for (int off = 16; off > 0; off >>= 1) {
            a0 += __shfl_xor_sync(0xffffffffu, a0, off);
            a1 += __shfl_xor_sync(0xffffffffu, a1, off);
            a2 += __shfl_xor_sync(0xffffffffu, a2, off);
            a3 += __shfl_xor_sync(0xffffffffu, a3, off);
        }

        // ALL lanes compute gates/c/h (warp-wide instr cost is identical;
        // c stays bitwise-identical across lanes) -> parallel publishes
        {
            float i_ = sig_acc(a0 + wg_cur.x);
            float f_ = sig_acc(a1 + wg_cur.y);
            float g_ = tanh_acc(a2 + wg_cur.z);
            float o_ = sig_acc(a3 + wg_cur.w);
            c = f_ * c + i_ * g_;
            float h = o_ * tanh_acc(c);   // finite, never NaN == sentinel-safe
            if (lane < NREP) {
                // lane r publishes replica r of this unit's padded line
                asm volatile("st.volatile.global.b32 [%0], %1;"
                             :: "l"(g_hp + (size_t)(s + 1) * HP_STRIDE
                                    + (size_t)lane * REP_STRIDE + cta * 32 + w),
                                "r"(__float_as_uint(h)) : "memory");
            } else if (lane == 4) {
                // dense copy for the classifier (off the critical path)
                asm volatile("st.global.cg.f32 [%0], %1;"
                             :: "l"(g_hd + (size_t)(s + 1) * 512 + u), "f"(h)
                             : "memory");
            }
        }
        wg_cur = wg_nxt;
        wg_nxt = wg_pf;
    }
}

// ---------------- host launch ----------------
extern "C" void kernel_launch(void* const* d_in, const int* in_sizes, int n_in,
                              void* d_out, int out_size) {
    (void)in_sizes; (void)n_in; (void)out_size;
    const int*   x          = (const int*)d_in[0];
    const int*   chars      = (const int*)d_in[1];
    const int*   char_lens  = (const int*)d_in[2];
    const float* word_embed = (const float*)d_in[3];
    const float* char_embed = (const float*)d_in[4];
    const float* c_Wih      = (const float*)d_in[5];
    const float* c_Whh      = (const float*)d_in[6];
    const float* c_bih      = (const float*)d_in[7];
    const float* c_bhh      = (const float*)d_in[8];
    const float* w_Wih      = (const float*)d_in[9];
    const float* w_Whh      = (const float*)d_in[10];
    const float* w_bih      = (const float*)d_in[11];
    const float* w_bhh      = (const float*)d_in[12];
    const float* cls_W      = (const float*)d_in[13];
    const float* cls_b      = (const float*)d_in[14];
    float* out = (float*)d_out;

    float *pA, *pWc, *pbc, *pgates, *pbw, *pF, *pwg, *phd;
    cudaGetSymbolAddress((void**)&pA,     g_A);
    cudaGetSymbolAddress((void**)&pWc,    g_Wc);
    cudaGetSymbolAddress((void**)&pbc,    g_bc);
    cudaGetSymbolAddress((void**)&pgates, g_gates);
    cudaGetSymbolAddress((void**)&pbw,    g_bw);
    cudaGetSymbolAddress((void**)&pF,     g_F);
    cudaGetSymbolAddress((void**)&pwg,    g_wg);
    cudaGetSymbolAddress((void**)&phd,    g_hd);

    prep_kernel<<<2048, 256>>>(chars, char_embed, c_Wih, c_Whh,
                               c_bih, c_bhh, w_bih, w_bhh);

    // char LSTM: 16 x (gates GEMM + pointwise)
    for (int t = 0; t < L_CHARS; t++) {
        gemm_bias<<<dim3(S_LEN / 128, 512 / 64), 256>>>(
            pA, pWc, pbc, pgates, CK, 512, 0);
        char_pointwise<<<(S_LEN * CHAR_HID) / 256, 256>>>(
            chars, char_lens, char_embed, t);
    }

    // word features + input-gate precompute (unit-blocked, biases folded)
    feats_kernel<<<(S_LEN * WK + 255) / 256, 256>>>(x, word_embed);
    gemm_bias<<<dim3(S_LEN / 128, 2048 / 64), 256>>>(
        pF, w_Wih, pbw, pwg, WK, 2048, 1);

    // sequential word LSTM (persistent, replicated sentinel-line dataflow)
    word_lstm_kernel<<<GW2, TPB2>>>(w_Whh);

    // classifier: out = h_all @ cls_W^T + cls_b  (dense h, offset one row)
    gemm_bias<<<dim3(S_LEN / 128, 1), 256>>>(
        phd + 512, cls_W, cls_b, out, 512, N_TAG, 0);
}

// round 14
// speedup vs baseline: 1.3626x; 1.1915x over previous
#include <cuda_runtime.h>
#include <cuda_bf16.h>
#include <math.h>

// ---------------- problem constants ----------------
#define S_LEN   8192
#define L_CHARS 16
#define CHAR_DIM 64
#define WORD_DIM 256
#define CHAR_HID 128
#define WORD_HID 512
#define N_TAG   64
#define CK      192              // CHAR_DIM + CHAR_HID (char gemm K)
#define WK      384              // WORD_DIM + CHAR_HID (word input gemm K)
#define GW2     128              // persistent CTAs for word LSTM (1/SM, <=148)
#define TPB2    128              // 4 warps = 4 hidden units per CTA (1 warp/SMSP)
#define SENT    0x7fbadbadu     // NaN-pattern sentinel (h can never be NaN)
#define NREP    4                // publish-line replicas (readers/line: 32)
#define REP_STRIDE 4096          // floats per replica (128 chunks x 32)
#define HP_STRIDE (NREP * REP_STRIDE)   // padded h row: 16384 floats
#define RING    8                // ring rows: 512KB total -> L2-resident forever

// ---------------- device scratch (no cudaMalloc allowed) ----------------
__device__ __align__(16) float g_A[S_LEN * CK];        // char gemm input [ce_t | h]
__device__ __align__(16) float g_gates[S_LEN * 512];   // char gates
__device__ __align__(16) float g_c[S_LEN * CHAR_HID];  // char cell state
__device__ __align__(16) float g_cf[S_LEN * CHAR_HID]; // char features
__device__ __align__(16) float g_Wc[512 * CK];         // concat [c_Wih | c_Whh]
__device__ __align__(16) float g_bc[512];              // c_bih + c_bhh
__device__ __align__(16) float g_bw[2048];             // w_bih + w_bhh
__device__ __align__(16) float g_F[S_LEN * WK];        // word feats [we | cf]
__device__ __align__(16) float g_wg[S_LEN * 2048];     // word input gates (unit f4)
__device__ __align__(16) float g_hp[RING * HP_STRIDE]; // RING of replicated h rows
__device__ __align__(16) float g_hd[(S_LEN + 1) * 512];// dense h (classifier)

__device__ __forceinline__ float sigmoidf_(float x) { return 1.f / (1.f + expf(-x)); }

// Accurate fast activations (2-ulp MUFU exp + fast divide).
// tanh.approx.f32 (5e-4 abs err) amplifies ~600x through the 8192-step
// recurrence -> 0.316 rel_err (R4). These stay at ~1e-7 per step.
__device__ __forceinline__ float sig_acc(float x) {
    x = fminf(fmaxf(x, -30.f), 30.f);
    float e = __expf(-x);
    return __fdividef(1.f, 1.f + e);
}
__device__ __forceinline__ float tanh_acc(float x) {
    x = fminf(fmaxf(x, -15.f), 15.f);
    float e = __expf(2.f * x);
    return __fdividef(e - 1.f, e + 1.f);
}
__device__ __forceinline__ float4 ldcg_f4(const float* p) {
    float4 v;
    asm volatile("ld.global.cg.v4.f32 {%0,%1,%2,%3}, [%4];"
                 : "=f"(v.x), "=f"(v.y), "=f"(v.z), "=f"(v.w) : "l"(p) : "memory");
    return v;
}
// VOLATILE poll load (ptxas may legally hoist weak loads out of spin loops --
// the R6 failure). Integer regs: no float compare on the NaN sentinel.
__device__ __forceinline__ uint4 ldvol_u4(const float* p) {
    uint4 v;
    asm volatile("ld.volatile.global.v4.b32 {%0,%1,%2,%3}, [%4];"
                 : "=r"(v.x), "=r"(v.y), "=r"(v.z), "=r"(v.w) : "l"(p) : "memory");
    return v;
}
__device__ __forceinline__ unsigned any_sent_u(uint4 v) {
    return (unsigned)(v.x == SENT) | (unsigned)(v.y == SENT) |
           (unsigned)(v.z == SENT) | (unsigned)(v.w == SENT);
}

// ---------------- prep: concat weights, biases, init buffers ----------------
__global__ void prep_kernel(const int* __restrict__ chars,
                            const float* __restrict__ char_embed,
                            const float* __restrict__ c_Wih,
                            const float* __restrict__ c_Whh,
                            const float* __restrict__ c_bih,
                            const float* __restrict__ c_bhh,
                            const float* __restrict__ w_bih,
                            const float* __restrict__ w_bhh) {
    size_t tid = blockIdx.x * blockDim.x + threadIdx.x;
    size_t stride = (size_t)gridDim.x * blockDim.x;
    for (size_t i = tid; i < 512 * CK; i += stride) {
        int j = (int)(i / CK), k = (int)(i - (size_t)j * CK);
        g_Wc[i] = (k < CHAR_DIM) ? c_Wih[j * CHAR_DIM + k]
                                 : c_Whh[j * CHAR_HID + (k - CHAR_DIM)];
    }
    for (size_t i = tid; i < 512; i += stride) g_bc[i] = c_bih[i] + c_bhh[i];
    for (size_t i = tid; i < 2048; i += stride) g_bw[i] = w_bih[i] + w_bhh[i];
    for (size_t i = tid; i < S_LEN * CHAR_HID; i += stride) g_c[i] = 0.f;
    // ring: slot 0 = zeros (h[0], all replicas), slots 1..RING-1 = sentinel
    // (re-initialized on every launch / graph replay)
    for (size_t i = tid; i < (size_t)RING * HP_STRIDE; i += stride)
        ((unsigned*)g_hp)[i] = (i < HP_STRIDE) ? 0u : SENT;
    for (size_t i = tid; i < 512; i += stride) g_hd[i] = 0.f;  // dense row 0
    // char gemm input for t=0: ce in cols [0,64), zeros (h0) in [64,192)
    for (size_t i = tid; i < S_LEN * CK; i += stride) {
        int b = (int)(i / CK), k = (int)(i - (size_t)b * CK);
        g_A[i] = (k < CHAR_DIM)
                   ? char_embed[chars[b * L_CHARS + 0] * CHAR_DIM + k]
                   : 0.f;
    }
}

// ---------------- generic fp32 GEMM: C = A(MxK) * B(NxK)^T + bias ----------------
// BM=128 BN=64 BK=16, 256 threads, 8x4 per-thread tile.
// mode 0: C[row*ldc+col] = acc + bias[col]
// mode 1: word-gate unit-blocked store: dst = (col&511)*4 + (col>>9)
__global__ void __launch_bounds__(256) gemm_bias(const float* __restrict__ A,
                                                 const float* __restrict__ B,
                                                 const float* __restrict__ bias,
                                                 float* __restrict__ C,
                                                 int K, int ldc, int mode) {
    __shared__ float sA[2][16][129];
    __shared__ float sB[2][16][65];
    const int bm = blockIdx.x << 7;
    const int bn = blockIdx.y << 6;
    const int tid = threadIdx.x;
    const int tx = tid & 15;
    const int ty = tid >> 4;
    const int lrow = tid >> 2;
    const int kq = (tid & 3) << 2;

    const float* Aptr = A + (size_t)(bm + lrow) * K + kq;
    const float* Bptr = B + (size_t)(bn + lrow) * K + kq;

    float acc[8][4];
#pragma unroll
    for (int i = 0; i < 8; i++)
#pragma unroll
        for (int j = 0; j < 4; j++) acc[i][j] = 0.f;

    {
        float4 v0 = *(const float4*)(Aptr);
        float4 v1 = *(const float4*)(Aptr + (size_t)64 * K);
        float4 vb = *(const float4*)(Bptr);
        sA[0][kq + 0][lrow] = v0.x; sA[0][kq + 1][lrow] = v0.y;
        sA[0][kq + 2][lrow] = v0.z; sA[0][kq + 3][lrow] = v0.w;
        sA[0][kq + 0][lrow + 64] = v1.x; sA[0][kq + 1][lrow + 64] = v1.y;
        sA[0][kq + 2][lrow + 64] = v1.z; sA[0][kq + 3][lrow + 64] = v1.w;
        sB[0][kq + 0][lrow] = vb.x; sB[0][kq + 1][lrow] = vb.y;
        sB[0][kq + 2][lrow] = vb.z; sB[0][kq + 3][lrow] = vb.w;
    }
    __syncthreads();

    const int nk = K >> 4;
    for (int kt = 0; kt < nk; kt++) {
        const int cur = kt & 1;
        float4 v0, v1, vb;
        const bool pf = (kt + 1) < nk;
        if (pf) {
            const float* Ap = Aptr + ((kt + 1) << 4);
            v0 = *(const float4*)(Ap);
            v1 = *(const float4*)(Ap + (size_t)64 * K);
            vb = *(const float4*)(Bptr + ((kt + 1) << 4));
        }
#pragma unroll
        for (int kk = 0; kk < 16; kk++) {
            float a[8], b[4];
#pragma unroll
            for (int i = 0; i < 8; i++) a[i] = sA[cur][kk][ty + 16 * i];
#pragma unroll
            for (int j = 0; j < 4; j++) b[j] = sB[cur][kk][tx + 16 * j];
#pragma unroll
            for (int i = 0; i < 8; i++)
#pragma unroll
                for (int j = 0; j < 4; j++)
                    acc[i][j] = fmaf(a[i], b[j], acc[i][j]);
        }
        if (pf) {
            const int nb = cur ^ 1;
            sA[nb][kq + 0][lrow] = v0.x; sA[nb][kq + 1][lrow] = v0.y;
            sA[nb][kq + 2][lrow] = v0.z; sA[nb][kq + 3][lrow] = v0.w;
            sA[nb][kq + 0][lrow + 64] = v1.x; sA[nb][kq + 1][lrow + 64] = v1.y;
            sA[nb][kq + 2][lrow + 64] = v1.z; sA[nb][kq + 3][lrow + 64] = v1.w;
            sB[nb][kq + 0][lrow] = vb.x; sB[nb][kq + 1][lrow] = vb.y;
            sB[nb][kq + 2][lrow] = vb.z; sB[nb][kq + 3][lrow] = vb.w;
        }
        __syncthreads();
    }

    if (mode == 0) {
#pragma unroll
        for (int i = 0; i < 8; i++) {
            int row = bm + ty + 16 * i;
#pragma unroll
            for (int j = 0; j < 4; j++) {
                int col = bn + tx + 16 * j;
                C[(size_t)row * ldc + col] = acc[i][j] + bias[col];
            }
        }
    } else {
        // unit-blocked: memory [u*4 + gt] per row, u = col&511, gt = col>>9
#pragma unroll
        for (int i = 0; i < 8; i++) {
            int row = bm + ty + 16 * i;
#pragma unroll
            for (int j = 0; j < 4; j++) {
                int col = bn + tx + 16 * j;
                int dst = (col & 511) * 4 + (col >> 9);
                C[(size_t)row * 2048 + dst] = acc[i][j] + bias[col];
            }
        }
    }
}

// ---------------- char LSTM pointwise update ----------------
__global__ void char_pointwise(const int* __restrict__ chars,
                               const int* __restrict__ char_lens,
                               const float* __restrict__ char_embed, int t) {
    int idx = blockIdx.x * blockDim.x + threadIdx.x;
    if (idx < S_LEN * CHAR_HID) {
        int b = idx >> 7, j = idx & 127;
        const float* gr = g_gates + b * 512;
        float i_ = sigmoidf_(gr[j]);
        float f_ = sigmoidf_(gr[128 + j]);
        float gg = tanhf(gr[256 + j]);
        float o_ = sigmoidf_(gr[384 + j]);
        float c = f_ * g_c[idx] + i_ * gg;
        g_c[idx] = c;
        float h = o_ * tanhf(c);
        g_A[b * CK + CHAR_DIM + j] = h;               // input for next step
        if (char_lens[b] - 1 == t) g_cf[idx] = h;     // final char feature
    }
    if (t + 1 < L_CHARS && idx < S_LEN * CHAR_DIM) {
        int b = idx >> 6, k = idx & 63;
        g_A[b * CK + k] = char_embed[chars[b * L_CHARS + (t + 1)] * CHAR_DIM + k];
    }
}

// ---------------- word feature gather ----------------
__global__ void feats_kernel(const int* __restrict__ x,
                             const float* __restrict__ word_embed) {
    int i = blockIdx.x * blockDim.x + threadIdx.x;
    if (i < S_LEN * WK) {
        int s = i / WK, k = i - s * WK;
        g_F[i] = (k < WORD_DIM) ? word_embed[x[s] * WORD_DIM + k]
                                : g_cf[s * CHAR_HID + (k - WORD_DIM)];
    }
}

// ---------------- persistent word LSTM recurrence ----------------
// GW2=128 CTAs x 4 warps, warp <-> hidden unit (1 warp/SMSP; R12 layout).
// SENTINEL-IN-PADDED-LINES sync, now on an 8-row RING (512KB -> permanently
// L2-resident: kills the DRAM cold-miss on every poll line AND the partial-
// sector allocate-fetch on every publish store that the 537MB linear layout
// caused). Slot(s) = s&7. At step s each thread also RE-POISONS its poll
// address in slot (s+4)&7 (currently row s-4): safe because reaching step s
// proves all CTAs finished step s-1 (skew <= 1 step -> row s-4 consumed by
// all), and the first real store to row s+4 comes >= 1 full step (~2000cy)
// after the poison -- no fence needed; poison & publish are both volatile
// (program-ordered per thread). 4x replication kept from R13 (neutral).
__global__ void __launch_bounds__(TPB2) word_lstm_kernel(const float* __restrict__ Whh) {
    __shared__ float sbuf[2][512];        // double-buffered dense h row

    const int cta = blockIdx.x;
    const int tid = threadIdx.x;
    const int w = tid >> 5;               // local unit 0..3
    const int lane = tid & 31;
    const int u = cta * 4 + w;            // global hidden unit 0..511

    // register-resident W_hh: wreg[gt][i] = Whh[(gt*512+u)*512 + i*32 + lane]
    float wreg[4][16];
#pragma unroll
    for (int gt = 0; gt < 4; gt++) {
        const float* p = Whh + (size_t)(gt * 512 + u) * 512 + lane;
#pragma unroll
        for (int i = 0; i < 16; i++) wreg[gt][i] = p[i * 32];
    }

    float c = 0.f;
    // all lanes load the same wg float4 (coalesced broadcast) so every lane
    // can compute the gate activations and c/h redundantly
    float4 wg_cur = *(const float4*)(g_wg + (size_t)0 * 2048 + u * 4);
    float4 wg_nxt = *(const float4*)(g_wg + (size_t)1 * 2048 + u * 4);

    const size_t my_rep = (size_t)(cta & (NREP - 1)) * REP_STRIDE;
    const size_t my_off = my_rep + (size_t)tid * 32;   // poll/poison offset

    for (int s = 0; s < S_LEN; s++) {
        // prefetch input gates two steps ahead (hidden under the wait)
        float4 wg_pf = make_float4(0.f, 0.f, 0.f, 0.f);
        if (s + 2 < S_LEN)
            wg_pf = ldcg_f4(g_wg + (size_t)(s + 2) * 2048 + u * 4);

        // poll chunk tid of ring slot (s&7) -- always L2-resident
        {
            const float* cp = g_hp + (size_t)(s & (RING - 1)) * HP_STRIDE + my_off;
            uint4 a;
            do {
                a = ldvol_u4(cp);
            } while (any_sent_u(a));
            *(float4*)&sbuf[s & 1][tid * 4] =
                make_float4(__uint_as_float(a.x), __uint_as_float(a.y),
                            __uint_as_float(a.z), __uint_as_float(a.w));
        }

        // re-poison future slot (s+4)&7 for row s+4 (holds consumed row s-4)
        if (s + 4 <= S_LEN) {
            unsigned sv = SENT;
            asm volatile("st.volatile.global.v4.b32 [%0], {%1,%1,%1,%1};"
                         :: "l"(g_hp + (size_t)((s + 4) & (RING - 1)) * HP_STRIDE
                                + my_off),
                            "r"(sv) : "memory");
        }
        __syncthreads();                  // h[s] staged in smem

        // conflict-free stride-32 h read
        const float* hrow = sbuf[s & 1];
        float hv[16];
#pragma unroll
        for (int i = 0; i < 16; i++) hv[i] = hrow[i * 32 + lane];

        float a0 = 0.f, a1 = 0.f, a2 = 0.f, a3 = 0.f;
#pragma unroll
        for (int i = 0; i < 16; i++) {
            a0 = fmaf(wreg[0][i], hv[i], a0);
            a1 = fmaf(wreg[1][i], hv[i], a1);
            a2 = fmaf(wreg[2][i], hv[i], a2);
            a3 = fmaf(wreg[3][i], hv[i], a3);
        }

        // full-warp butterfly reduce (4 values) -> every lane holds a0..a3
#pragma unroll
        for (int off = 16; off > 0; off >>= 1) {
            a0 += __shfl_xor_sync(0xffffffffu, a0, off);
            a1 += __shfl_xor_sync(0xffffffffu, a1, off);
            a2 += __shfl_xor_sync(0xffffffffu, a2, off);
            a3 += __shfl_xor_sync(0xffffffffu, a3, off);
        }

        // ALL lanes compute gates/c/h (warp-wide instr cost is identical;
        // c stays bitwise-identical across lanes) -> parallel publishes
        {
            float i_ = sig_acc(a0 + wg_cur.x);
            float f_ = sig_acc(a1 + wg_cur.y);
            float g_ = tanh_acc(a2 + wg_cur.z);
            float o_ = sig_acc(a3 + wg_cur.w);
            c = f_ * c + i_ * g_;
            float h = o_ * tanh_acc(c);   // finite, never NaN == sentinel-safe
            if (lane < NREP) {
                // lane r publishes replica r into ring slot (s+1)&7
                asm volatile("st.volatile.global.b32 [%0], %1;"
                             :: "l"(g_hp + (size_t)((s + 1) & (RING - 1)) * HP_STRIDE
                                    + (size_t)lane * REP_STRIDE + cta * 32 + w),
                                "r"(__float_as_uint(h)) : "memory");
            } else if (lane == 4) {
                // dense copy for the classifier (off the critical path)
                asm volatile("st.global.cg.f32 [%0], %1;"
                             :: "l"(g_hd + (size_t)(s + 1) * 512 + u), "f"(h)
                             : "memory");
            }
        }
        wg_cur = wg_nxt;
        wg_nxt = wg_pf;
    }
}

// ---------------- host launch ----------------
extern "C" void kernel_launch(void* const* d_in, const int* in_sizes, int n_in,
                              void* d_out, int out_size) {
    (void)in_sizes; (void)n_in; (void)out_size;
    const int*   x          = (const int*)d_in[0];
    const int*   chars      = (const int*)d_in[1];
    const int*   char_lens  = (const int*)d_in[2];
    const float* word_embed = (const float*)d_in[3];
    const float* char_embed = (const float*)d_in[4];
    const float* c_Wih      = (const float*)d_in[5];
    const float* c_Whh      = (const float*)d_in[6];
    const float* c_bih      = (const float*)d_in[7];
    const float* c_bhh      = (const float*)d_in[8];
    const float* w_Wih      = (const float*)d_in[9];
    const float* w_Whh      = (const float*)d_in[10];
    const float* w_bih      = (const float*)d_in[11];
    const float* w_bhh      = (const float*)d_in[12];
    const float* cls_W      = (const float*)d_in[13];
    const float* cls_b      = (const float*)d_in[14];
    float* out = (float*)d_out;

    float *pA, *pWc, *pbc, *pgates, *pbw, *pF, *pwg, *phd;
    cudaGetSymbolAddress((void**)&pA,     g_A);
    cudaGetSymbolAddress((void**)&pWc,    g_Wc);
    cudaGetSymbolAddress((void**)&pbc,    g_bc);
    cudaGetSymbolAddress((void**)&pgates, g_gates);
    cudaGetSymbolAddress((void**)&pbw,    g_bw);
    cudaGetSymbolAddress((void**)&pF,     g_F);
    cudaGetSymbolAddress((void**)&pwg,    g_wg);
    cudaGetSymbolAddress((void**)&phd,    g_hd);

    prep_kernel<<<1024, 256>>>(chars, char_embed, c_Wih, c_Whh,
                               c_bih, c_bhh, w_bih, w_bhh);

    // char LSTM: 16 x (gates GEMM + pointwise)
    for (int t = 0; t < L_CHARS; t++) {
        gemm_bias<<<dim3(S_LEN / 128, 512 / 64), 256>>>(
            pA, pWc, pbc, pgates, CK, 512, 0);
        char_pointwise<<<(S_LEN * CHAR_HID) / 256, 256>>>(
            chars, char_lens, char_embed, t);
    }

    // word features + input-gate precompute (unit-blocked, biases folded)
    feats_kernel<<<(S_LEN * WK + 255) / 256, 256>>>(x, word_embed);
    gemm_bias<<<dim3(S_LEN / 128, 2048 / 64), 256>>>(
        pF, w_Wih, pbw, pwg, WK, 2048, 1);

    // sequential word LSTM (persistent, L2-resident ring sentinel dataflow)
    word_lstm_kernel<<<GW2, TPB2>>>(w_Whh);

    // classifier: out = h_all @ cls_W^T + cls_b  (dense h, offset one row)
    gemm_bias<<<dim3(S_LEN / 128, 1), 256>>>(
        phd + 512, cls_W, cls_b, out, 512, N_TAG, 0);
}

// round 15
// speedup vs baseline: 1.3978x; 1.0258x over previous
#include <cuda_runtime.h>
#include <cuda_bf16.h>
#include <math.h>

// ---------------- problem constants ----------------
#define S_LEN   8192
#define L_CHARS 16
#define CHAR_DIM 64
#define WORD_DIM 256
#define CHAR_HID 128
#define WORD_HID 512
#define N_TAG   64
#define CK      192              // CHAR_DIM + CHAR_HID (char gemm K)
#define WK      384              // WORD_DIM + CHAR_HID (word input gemm K)
#define GW2     128              // persistent CTAs for word LSTM (1/SM, <=148)
#define TPB2    128              // 4 warps = 4 hidden units per CTA (1 warp/SMSP)
#define SENT    0x7fbadbadu     // NaN-pattern sentinel (h can never be NaN)
#define NREP    4                // publish-line replicas (readers/line: 32)
#define REP_STRIDE 4096          // floats per replica (128 chunks x 32)
#define HP_STRIDE (NREP * REP_STRIDE)   // padded h row: 16384 floats
#define RING    8                // ring rows: 512KB total -> L2-resident forever

// ---------------- device scratch (no cudaMalloc allowed) ----------------
__device__ __align__(16) float g_A[S_LEN * CK];        // char gemm input [ce_t | h]
__device__ __align__(16) float g_gates[S_LEN * 512];   // char gates
__device__ __align__(16) float g_c[S_LEN * CHAR_HID];  // char cell state
__device__ __align__(16) float g_cf[S_LEN * CHAR_HID]; // char features
__device__ __align__(16) float g_Wc[512 * CK];         // concat [c_Wih | c_Whh]
__device__ __align__(16) float g_bc[512];              // c_bih + c_bhh
__device__ __align__(16) float g_bw[2048];             // w_bih + w_bhh
__device__ __align__(16) float g_F[S_LEN * WK];        // word feats [we | cf]
__device__ __align__(16) float g_wg[S_LEN * 2048];     // word input gates (unit f4)
__device__ __align__(16) float g_hp[RING * HP_STRIDE]; // RING of replicated h rows
__device__ __align__(16) float g_hd[(S_LEN + 1) * 512];// dense h (classifier)

__device__ __forceinline__ float sigmoidf_(float x) { return 1.f / (1.f + expf(-x)); }

// Accurate fast activations (2-ulp MUFU exp + fast divide).
// tanh.approx.f32 (5e-4 abs err) amplifies ~600x through the 8192-step
// recurrence -> 0.316 rel_err (R4). These stay at ~1e-7 per step.
__device__ __forceinline__ float sig_acc(float x) {
    x = fminf(fmaxf(x, -30.f), 30.f);
    float e = __expf(-x);
    return __fdividef(1.f, 1.f + e);
}
__device__ __forceinline__ float tanh_acc(float x) {
    x = fminf(fmaxf(x, -15.f), 15.f);
    float e = __expf(2.f * x);
    return __fdividef(e - 1.f, e + 1.f);
}
__device__ __forceinline__ float4 ldcg_f4(const float* p) {
    float4 v;
    asm volatile("ld.global.cg.v4.f32 {%0,%1,%2,%3}, [%4];"
                 : "=f"(v.x), "=f"(v.y), "=f"(v.z), "=f"(v.w) : "l"(p) : "memory");
    return v;
}
// VOLATILE poll load (ptxas may legally hoist weak loads out of spin loops --
// the R6 failure). Integer regs: no float compare on the NaN sentinel.
__device__ __forceinline__ uint4 ldvol_u4(const float* p) {
    uint4 v;
    asm volatile("ld.volatile.global.v4.b32 {%0,%1,%2,%3}, [%4];"
                 : "=r"(v.x), "=r"(v.y), "=r"(v.z), "=r"(v.w) : "l"(p) : "memory");
    return v;
}
__device__ __forceinline__ unsigned any_sent_u(uint4 v) {
    return (unsigned)(v.x == SENT) | (unsigned)(v.y == SENT) |
           (unsigned)(v.z == SENT) | (unsigned)(v.w == SENT);
}

// ---------------- prep: concat weights, biases, init buffers ----------------
__global__ void prep_kernel(const int* __restrict__ chars,
                            const float* __restrict__ char_embed,
                            const float* __restrict__ c_Wih,
                            const float* __restrict__ c_Whh,
                            const float* __restrict__ c_bih,
                            const float* __restrict__ c_bhh,
                            const float* __restrict__ w_bih,
                            const float* __restrict__ w_bhh) {
    size_t tid = blockIdx.x * blockDim.x + threadIdx.x;
    size_t stride = (size_t)gridDim.x * blockDim.x;
    for (size_t i = tid; i < 512 * CK; i += stride) {
        int j = (int)(i / CK), k = (int)(i - (size_t)j * CK);
        g_Wc[i] = (k < CHAR_DIM) ? c_Wih[j * CHAR_DIM + k]
                                 : c_Whh[j * CHAR_HID + (k - CHAR_DIM)];
    }
    for (size_t i = tid; i < 512; i += stride) g_bc[i] = c_bih[i] + c_bhh[i];
    for (size_t i = tid; i < 2048; i += stride) g_bw[i] = w_bih[i] + w_bhh[i];
    for (size_t i = tid; i < S_LEN * CHAR_HID; i += stride) g_c[i] = 0.f;
    // ring: slot 0 = zeros (h[0], all replicas), slots 1..RING-1 = sentinel
    // (re-initialized on every launch / graph replay)
    for (size_t i = tid; i < (size_t)RING * HP_STRIDE; i += stride)
        ((unsigned*)g_hp)[i] = (i < HP_STRIDE) ? 0u : SENT;
    for (size_t i = tid; i < 512; i += stride) g_hd[i] = 0.f;  // dense row 0
    // char gemm input for t=0: ce in cols [0,64), zeros (h0) in [64,192)
    for (size_t i = tid; i < S_LEN * CK; i += stride) {
        int b = (int)(i / CK), k = (int)(i - (size_t)b * CK);
        g_A[i] = (k < CHAR_DIM)
                   ? char_embed[chars[b * L_CHARS + 0] * CHAR_DIM + k]
                   : 0.f;
    }
}

// ---------------- generic fp32 GEMM: C = A(MxK) * B(NxK)^T + bias ----------------
// BM=128 BN=64 BK=16, 256 threads, 8x4 per-thread tile.
// mode 0: C[row*ldc+col] = acc + bias[col]
// mode 1: word-gate unit-blocked store: dst = (col&511)*4 + (col>>9)
__global__ void __launch_bounds__(256) gemm_bias(const float* __restrict__ A,
                                                 const float* __restrict__ B,
                                                 const float* __restrict__ bias,
                                                 float* __restrict__ C,
                                                 int K, int ldc, int mode) {
    __shared__ float sA[2][16][129];
    __shared__ float sB[2][16][65];
    const int bm = blockIdx.x << 7;
    const int bn = blockIdx.y << 6;
    const int tid = threadIdx.x;
    const int tx = tid & 15;
    const int ty = tid >> 4;
    const int lrow = tid >> 2;
    const int kq = (tid & 3) << 2;

    const float* Aptr = A + (size_t)(bm + lrow) * K + kq;
    const float* Bptr = B + (size_t)(bn + lrow) * K + kq;

    float acc[8][4];
#pragma unroll
    for (int i = 0; i < 8; i++)
#pragma unroll
        for (int j = 0; j < 4; j++) acc[i][j] = 0.f;

    {
        float4 v0 = *(const float4*)(Aptr);
        float4 v1 = *(const float4*)(Aptr + (size_t)64 * K);
        float4 vb = *(const float4*)(Bptr);
        sA[0][kq + 0][lrow] = v0.x; sA[0][kq + 1][lrow] = v0.y;
        sA[0][kq + 2][lrow] = v0.z; sA[0][kq + 3][lrow] = v0.w;
        sA[0][kq + 0][lrow + 64] = v1.x; sA[0][kq + 1][lrow + 64] = v1.y;
        sA[0][kq + 2][lrow + 64] = v1.z; sA[0][kq + 3][lrow + 64] = v1.w;
        sB[0][kq + 0][lrow] = vb.x; sB[0][kq + 1][lrow] = vb.y;
        sB[0][kq + 2][lrow] = vb.z; sB[0][kq + 3][lrow] = vb.w;
    }
    __syncthreads();

    const int nk = K >> 4;
    for (int kt = 0; kt < nk; kt++) {
        const int cur = kt & 1;
        float4 v0, v1, vb;
        const bool pf = (kt + 1) < nk;
        if (pf) {
            const float* Ap = Aptr + ((kt + 1) << 4);
            v0 = *(const float4*)(Ap);
            v1 = *(const float4*)(Ap + (size_t)64 * K);
            vb = *(const float4*)(Bptr + ((kt + 1) << 4));
        }
#pragma unroll
        for (int kk = 0; kk < 16; kk++) {
            float a[8], b[4];
#pragma unroll
            for (int i = 0; i < 8; i++) a[i] = sA[cur][kk][ty + 16 * i];
#pragma unroll
            for (int j = 0; j < 4; j++) b[j] = sB[cur][kk][tx + 16 * j];
#pragma unroll
            for (int i = 0; i < 8; i++)
#pragma unroll
                for (int j = 0; j < 4; j++)
                    acc[i][j] = fmaf(a[i], b[j], acc[i][j]);
        }
        if (pf) {
            const int nb = cur ^ 1;
            sA[nb][kq + 0][lrow] = v0.x; sA[nb][kq + 1][lrow] = v0.y;
            sA[nb][kq + 2][lrow] = v0.z; sA[nb][kq + 3][lrow] = v0.w;
            sA[nb][kq + 0][lrow + 64] = v1.x; sA[nb][kq + 1][lrow + 64] = v1.y;
            sA[nb][kq + 2][lrow + 64] = v1.z; sA[nb][kq + 3][lrow + 64] = v1.w;
            sB[nb][kq + 0][lrow] = vb.x; sB[nb][kq + 1][lrow] = vb.y;
            sB[nb][kq + 2][lrow] = vb.z; sB[nb][kq + 3][lrow] = vb.w;
        }
        __syncthreads();
    }

    if (mode == 0) {
#pragma unroll
        for (int i = 0; i < 8; i++) {
            int row = bm + ty + 16 * i;
#pragma unroll
            for (int j = 0; j < 4; j++) {
                int col = bn + tx + 16 * j;
                C[(size_t)row * ldc + col] = acc[i][j] + bias[col];
            }
        }
    } else {
        // unit-blocked: memory [u*4 + gt] per row, u = col&511, gt = col>>9
#pragma unroll
        for (int i = 0; i < 8; i++) {
            int row = bm + ty + 16 * i;
#pragma unroll
            for (int j = 0; j < 4; j++) {
                int col = bn + tx + 16 * j;
                int dst = (col & 511) * 4 + (col >> 9);
                C[(size_t)row * 2048 + dst] = acc[i][j] + bias[col];
            }
        }
    }
}

// ---------------- char LSTM pointwise update ----------------
__global__ void char_pointwise(const int* __restrict__ chars,
                               const int* __restrict__ char_lens,
                               const float* __restrict__ char_embed, int t) {
    int idx = blockIdx.x * blockDim.x + threadIdx.x;
    if (idx < S_LEN * CHAR_HID) {
        int b = idx >> 7, j = idx & 127;
        const float* gr = g_gates + b * 512;
        float i_ = sigmoidf_(gr[j]);
        float f_ = sigmoidf_(gr[128 + j]);
        float gg = tanhf(gr[256 + j]);
        float o_ = sigmoidf_(gr[384 + j]);
        float c = f_ * g_c[idx] + i_ * gg;
        g_c[idx] = c;
        float h = o_ * tanhf(c);
        g_A[b * CK + CHAR_DIM + j] = h;               // input for next step
        if (char_lens[b] - 1 == t) g_cf[idx] = h;     // final char feature
    }
    if (t + 1 < L_CHARS && idx < S_LEN * CHAR_DIM) {
        int b = idx >> 6, k = idx & 63;
        g_A[b * CK + k] = char_embed[chars[b * L_CHARS + (t + 1)] * CHAR_DIM + k];
    }
}

// ---------------- word feature gather ----------------
__global__ void feats_kernel(const int* __restrict__ x,
                             const float* __restrict__ word_embed) {
    int i = blockIdx.x * blockDim.x + threadIdx.x;
    if (i < S_LEN * WK) {
        int s = i / WK, k = i - s * WK;
        g_F[i] = (k < WORD_DIM) ? word_embed[x[s] * WORD_DIM + k]
                                : g_cf[s * CHAR_HID + (k - WORD_DIM)];
    }
}

// ---------------- persistent word LSTM recurrence ----------------
// GW2=128 CTAs x 4 warps, warp <-> hidden unit (1 warp/SMSP; R12 layout).
// SENTINEL-IN-PADDED-LINES sync on the 8-row L2-resident RING (R14).
// R15 change: the re-poison store is moved OFF the pre-bar critical path.
// In R14 each thread issued st.volatile.v4 between poll and __syncthreads
// (~128cy/warp of LSU issue delaying every warp's bar arrival, and the bar
// takes the max). Now poison is issued AFTER the publish, in the shadow of
// the next step's poll wait (idle latency -> the stores are free).
// Safety: poison targets slot (s+5)&7 (row s+5). A consumer polls row s+5
// only after detecting full row s+4, which requires OUR h[s+4] publish --
// 4 full steps (~8000cy) after this poison issues. The slot's occupant
// (row s-3) is provably consumed: reaching step s proves all CTAs passed
// step s-1 > s-3. Prep pre-poisons slots 1..7 (rows 1..7); step-s poison
// covers rows 5..8192 with per-thread program order vs our own publishes.
__global__ void __launch_bounds__(TPB2) word_lstm_kernel(const float* __restrict__ Whh) {
    __shared__ float sbuf[2][512];        // double-buffered dense h row

    const int cta = blockIdx.x;
    const int tid = threadIdx.x;
    const int w = tid >> 5;               // local unit 0..3
    const int lane = tid & 31;
    const int u = cta * 4 + w;            // global hidden unit 0..511

    // register-resident W_hh: wreg[gt][i] = Whh[(gt*512+u)*512 + i*32 + lane]
    float wreg[4][16];
#pragma unroll
    for (int gt = 0; gt < 4; gt++) {
        const float* p = Whh + (size_t)(gt * 512 + u) * 512 + lane;
#pragma unroll
        for (int i = 0; i < 16; i++) wreg[gt][i] = p[i * 32];
    }

    float c = 0.f;
    // all lanes load the same wg float4 (coalesced broadcast) so every lane
    // can compute the gate activations and c/h redundantly
    float4 wg_cur = *(const float4*)(g_wg + (size_t)0 * 2048 + u * 4);
    float4 wg_nxt = *(const float4*)(g_wg + (size_t)1 * 2048 + u * 4);

    const size_t my_rep = (size_t)(cta & (NREP - 1)) * REP_STRIDE;
    const size_t my_off = my_rep + (size_t)tid * 32;   // poll/poison offset

    for (int s = 0; s < S_LEN; s++) {
        // prefetch input gates two steps ahead (hidden under the wait)
        float4 wg_pf = make_float4(0.f, 0.f, 0.f, 0.f);
        if (s + 2 < S_LEN)
            wg_pf = ldcg_f4(g_wg + (size_t)(s + 2) * 2048 + u * 4);

        // poll chunk tid of ring slot (s&7) -- always L2-resident
        {
            const float* cp = g_hp + (size_t)(s & (RING - 1)) * HP_STRIDE + my_off;
            uint4 a;
            do {
                a = ldvol_u4(cp);
            } while (any_sent_u(a));
            *(float4*)&sbuf[s & 1][tid * 4] =
                make_float4(__uint_as_float(a.x), __uint_as_float(a.y),
                            __uint_as_float(a.z), __uint_as_float(a.w));
        }
        __syncthreads();                  // h[s] staged in smem

        // conflict-free stride-32 h read
        const float* hrow = sbuf[s & 1];
        float hv[16];
#pragma unroll
        for (int i = 0; i < 16; i++) hv[i] = hrow[i * 32 + lane];

        float a0 = 0.f, a1 = 0.f, a2 = 0.f, a3 = 0.f;
#pragma unroll
        for (int i = 0; i < 16; i++) {
            a0 = fmaf(wreg[0][i], hv[i], a0);
            a1 = fmaf(wreg[1][i], hv[i], a1);
            a2 = fmaf(wreg[2][i], hv[i], a2);
            a3 = fmaf(wreg[3][i], hv[i], a3);
        }

        // full-warp butterfly reduce (4 values) -> every lane holds a0..a3
#pragma unroll
        for (int off = 16; off > 0; off >>= 1) {
            a0 += __shfl_xor_sync(0xffffffffu, a0, off);
            a1 += __shfl_xor_sync(0xffffffffu, a1, off);
            a2 += __shfl_xor_sync(0xffffffffu, a2, off);
            a3 += __shfl_xor_sync(0xffffffffu, a3, off);
        }

        // ALL lanes compute gates/c/h (warp-wide instr cost is identical;
        // c stays bitwise-identical across lanes) -> parallel publishes
        {
            float i_ = sig_acc(a0 + wg_cur.x);
            float f_ = sig_acc(a1 + wg_cur.y);
            float g_ = tanh_acc(a2 + wg_cur.z);
            float o_ = sig_acc(a3 + wg_cur.w);
            c = f_ * c + i_ * g_;
            float h = o_ * tanh_acc(c);   // finite, never NaN == sentinel-safe
            if (lane < NREP) {
                // lane r publishes replica r into ring slot (s+1)&7
                asm volatile("st.volatile.global.b32 [%0], %1;"
                             :: "l"(g_hp + (size_t)((s + 1) & (RING - 1)) * HP_STRIDE
                                    + (size_t)lane * REP_STRIDE + cta * 32 + w),
                                "r"(__float_as_uint(h)) : "memory");
            } else if (lane == 4) {
                // dense copy for the classifier (off the critical path)
                asm volatile("st.global.cg.f32 [%0], %1;"
                             :: "l"(g_hd + (size_t)(s + 1) * 512 + u), "f"(h)
                             : "memory");
            }
        }

        // re-poison slot (s+5)&7 for row s+5 -- AFTER publish, hidden in the
        // shadow of the next step's poll wait (was pre-bar in R14)
        if (s + 5 <= S_LEN) {
            unsigned sv = SENT;
            asm volatile("st.volatile.global.v4.b32 [%0], {%1,%1,%1,%1};"
                         :: "l"(g_hp + (size_t)((s + 5) & (RING - 1)) * HP_STRIDE
                                + my_off),
                            "r"(sv) : "memory");
        }

        wg_cur = wg_nxt;
        wg_nxt = wg_pf;
    }
}

// ---------------- host launch ----------------
extern "C" void kernel_launch(void* const* d_in, const int* in_sizes, int n_in,
                              void* d_out, int out_size) {
    (void)in_sizes; (void)n_in; (void)out_size;
    const int*   x          = (const int*)d_in[0];
    const int*   chars      = (const int*)d_in[1];
    const int*   char_lens  = (const int*)d_in[2];
    const float* word_embed = (const float*)d_in[3];
    const float* char_embed = (const float*)d_in[4];
    const float* c_Wih      = (const float*)d_in[5];
    const float* c_Whh      = (const float*)d_in[6];
    const float* c_bih      = (const float*)d_in[7];
    const float* c_bhh      = (const float*)d_in[8];
    const float* w_Wih      = (const float*)d_in[9];
    const float* w_Whh      = (const float*)d_in[10];
    const float* w_bih      = (const float*)d_in[11];
    const float* w_bhh      = (const float*)d_in[12];
    const float* cls_W      = (const float*)d_in[13];
    const float* cls_b      = (const float*)d_in[14];
    float* out = (float*)d_out;

    float *pA, *pWc, *pbc, *pgates, *pbw, *pF, *pwg, *phd;
    cudaGetSymbolAddress((void**)&pA,     g_A);
    cudaGetSymbolAddress((void**)&pWc,    g_Wc);
    cudaGetSymbolAddress((void**)&pbc,    g_bc);
    cudaGetSymbolAddress((void**)&pgates, g_gates);
    cudaGetSymbolAddress((void**)&pbw,    g_bw);
    cudaGetSymbolAddress((void**)&pF,     g_F);
    cudaGetSymbolAddress((void**)&pwg,    g_wg);
    cudaGetSymbolAddress((void**)&phd,    g_hd);

    prep_kernel<<<1024, 256>>>(chars, char_embed, c_Wih, c_Whh,
                               c_bih, c_bhh, w_bih, w_bhh);

    // char LSTM: 16 x (gates GEMM + pointwise)
    for (int t = 0; t < L_CHARS; t++) {
        gemm_bias<<<dim3(S_LEN / 128, 512 / 64), 256>>>(
            pA, pWc, pbc, pgates, CK, 512, 0);
        char_pointwise<<<(S_LEN * CHAR_HID) / 256, 256>>>(
            chars, char_lens, char_embed, t);
    }

    // word features + input-gate precompute (unit-blocked, biases folded)
    feats_kernel<<<(S_LEN * WK + 255) / 256, 256>>>(x, word_embed);
    gemm_bias<<<dim3(S_LEN / 128, 2048 / 64), 256>>>(
        pF, w_Wih, pbw, pwg, WK, 2048, 1);

    // sequential word LSTM (persistent, L2-resident ring sentinel dataflow)
    word_lstm_kernel<<<GW2, TPB2>>>(w_Whh);

    // classifier: out = h_all @ cls_W^T + cls_b  (dense h, offset one row)
    gemm_bias<<<dim3(S_LEN / 128, 1), 256>>>(
        phd + 512, cls_W, cls_b, out, 512, N_TAG, 0);
}